// round 9
// baseline (speedup 1.0000x reference)
#include <cuda_runtime.h>

// ---------------- problem constants ----------------
#define NU 8000
#define NI 10000
#define NT 18000
#define G  4096
#define D  64
#define HD 64
#define OD 64
#define ALPHA 0.8f
#define EPSL  1e-8f

// ---------------- scratch (device globals; no allocation allowed) ----------------
__device__ float g_B[NT * G];        // group_weights^T  (18000 x 4096)  ~295 MB
__device__ float g_R2[NT * 128];     // [V_u | 0 ; 0 | V_i]              ~9.2 MB
__device__ float g_V[NT * HD];       // v projections
__device__ float g_E[NT];            // exp(s)
__device__ float g_Z[2 * G];         // per-half softmax denominators
__device__ int   g_cnt[2 * G];       // per-half unmasked counts
__device__ float g_wp[G * G];        // B^T B                           ~67 MB
__device__ float g_GF[G * 128];      // group_feats
__device__ float g_msg[G * 128];
__device__ float g_deg[G];
__device__ float g_norm[G];
__device__ float g_red[2 * 65];      // [r(64) | sum Ws] per half
__device__ float g_uvec[2 * D];
__device__ float g_ccon[2];

// ---------------- f32x2 helpers ----------------
__device__ __forceinline__ unsigned long long splat2(float x) {
    unsigned long long r;
    asm("mov.b64 %0, {%1, %1};" : "=l"(r) : "f"(x));
    return r;
}
__device__ __forceinline__ void fma2(unsigned long long& d, unsigned long long a, unsigned long long b) {
    asm("fma.rn.f32x2 %0, %1, %2, %0;" : "+l"(d) : "l"(a), "l"(b));
}
__device__ __forceinline__ void unpack2(unsigned long long v, float& lo, float& hi) {
    asm("mov.b64 {%0, %1}, %2;" : "=f"(lo), "=f"(hi) : "l"(v));
}

// ---------------- k_zero: clear accumulators ----------------
__global__ void k_zero() {
    int i = blockIdx.x * blockDim.x + threadIdx.x;
    if (i < 2 * 65) g_red[i] = 0.f;
    if (i < 2 * G) { g_Z[i] = 0.f; g_cnt[i] = 0; }
}

// ---------------- k_reduce: r = sum_m Ws[m] * x[m,:],  sw = sum Ws ----------------
__global__ void k_reduce(const float* __restrict__ x,
                         const float* __restrict__ uWs,
                         const float* __restrict__ iWs) {
    int half = blockIdx.y;
    int m0 = blockIdx.x * 500;
    int Nh = half ? NI : NU;
    if (m0 >= Nh) return;
    const float* Ws = half ? iWs : uWs;
    int off = half ? NU : 0;
    int md = threadIdx.x >> 6;   // 0..3
    int dd = threadIdx.x & 63;
    float acc = 0.f, sw = 0.f;
    int m1 = min(m0 + 500, Nh);
    for (int m = m0 + md; m < m1; m += 4) {
        float w = Ws[m];
        acc += w * x[(off + m) * D + dd];
        if (dd == 0) sw += w;
    }
    __shared__ float sA[4][64];
    __shared__ float sW[4];
    sA[md][dd] = acc;
    if (dd == 0) sW[md] = sw;
    __syncthreads();
    if (md == 0) {
        float t = sA[0][dd] + sA[1][dd] + sA[2][dd] + sA[3][dd];
        atomicAdd(&g_red[half * 65 + dd], t);
        if (dd == 0) atomicAdd(&g_red[half * 65 + 64], sW[0] + sW[1] + sW[2] + sW[3]);
    }
}

// ---------------- k_prep: t = Wk r + sw*bk ; uvec = Wq^T t ; c = bq.t + bs ----------------
__global__ void k_prep(const float* __restrict__ uWk, const float* __restrict__ ubk,
                       const float* __restrict__ uWq, const float* __restrict__ ubq,
                       const float* __restrict__ ubs,
                       const float* __restrict__ iWk, const float* __restrict__ ibk,
                       const float* __restrict__ iWq, const float* __restrict__ ibq,
                       const float* __restrict__ ibs) {
    __shared__ float rS[64], tS[64];
    int t = threadIdx.x;
    for (int half = 0; half < 2; half++) {
        const float* Wk = half ? iWk : uWk; const float* bk = half ? ibk : ubk;
        const float* Wq = half ? iWq : uWq; const float* bq = half ? ibq : ubq;
        const float* bs = half ? ibs : ubs;
        rS[t] = g_red[half * 65 + t];
        __syncthreads();
        float sw = g_red[half * 65 + 64];
        float tv = 0.f;
        for (int d = 0; d < D; d++) tv += Wk[t * D + d] * rS[d];
        tv += sw * bk[t];
        tS[t] = tv;
        __syncthreads();
        float u = 0.f;
        for (int hd = 0; hd < HD; hd++) u += Wq[hd * D + t] * tS[hd];
        g_uvec[half * 64 + t] = u;
        if (t == 0) {
            float c = bs[0];
            for (int hd = 0; hd < HD; hd++) c += bq[hd] * tS[hd];
            g_ccon[half] = c;
        }
        __syncthreads();
    }
}

// ---------------- k_ev: per-row E[n]=exp(s[n]), V row, R2 row ----------------
__global__ void k_ev(const float* __restrict__ x,
                     const float* __restrict__ uWv, const float* __restrict__ ubv,
                     const float* __restrict__ iWv, const float* __restrict__ ibv) {
    int n = blockIdx.x;
    int half = (n >= NU) ? 1 : 0;
    const float* Wv = half ? iWv : uWv;
    const float* bv = half ? ibv : ubv;
    __shared__ float xs[64];
    __shared__ float ps[64];
    int t = threadIdx.x;
    xs[t] = x[n * D + t];
    __syncthreads();
    float v = bv[t];
    #pragma unroll
    for (int d = 0; d < D; d++) v += Wv[t * D + d] * xs[d];
    g_V[n * HD + t] = v;
    if (half == 0) { g_R2[n * 128 + t] = v;   g_R2[n * 128 + 64 + t] = 0.f; }
    else           { g_R2[n * 128 + t] = 0.f; g_R2[n * 128 + 64 + t] = v;  }
    ps[t] = xs[t] * g_uvec[half * 64 + t];
    __syncthreads();
    if (t < 32) ps[t] += ps[t + 32];
    __syncwarp();
    if (t == 0) {
        float s = 0.f;
        #pragma unroll
        for (int i = 0; i < 32; i++) s += ps[i];
        g_E[n] = expf(s + g_ccon[half]);
    }
}

// ---------------- k_z: Z_g and counts per half ----------------
__global__ void k_z(const int* __restrict__ H) {
    int gcol = blockIdx.x * 256 + threadIdx.x;
    int n0 = blockIdx.y * 1000;
    int half = (n0 >= NU) ? 1 : 0;
    __shared__ float eS[1000];
    for (int i = threadIdx.x; i < 1000; i += 256) eS[i] = g_E[n0 + i];
    __syncthreads();
    float z = 0.f; int c = 0;
    const int* Hp = H + n0 * G + gcol;
    for (int i = 0; i < 1000; i++) {
        if (Hp[i * G] != 0) { z += eS[i]; c++; }
    }
    atomicAdd(&g_Z[half * G + gcol], z);
    atomicAdd(&g_cnt[half * G + gcol], c);
}

// ---------------- k_b: build B[n,g] = softmax weight (transposed) ----------------
__global__ void k_b(const int* __restrict__ H) {
    int gcol = blockIdx.x * 256 + threadIdx.x;
    int n0 = blockIdx.y * 1000;
    int half = (n0 >= NU) ? 1 : 0;
    __shared__ float eS[1000];
    for (int i = threadIdx.x; i < 1000; i += 256) eS[i] = g_E[n0 + i];
    __syncthreads();
    int cnt = g_cnt[half * G + gcol];
    float invZ = (cnt > 0) ? 1.f / g_Z[half * G + gcol] : 0.f;
    float uni = 1.f / (half ? (float)NI : (float)NU);
    const int* Hp = H + n0 * G + gcol;
    float* Bp = g_B + n0 * G + gcol;
    for (int i = 0; i < 1000; i++) {
        int h = Hp[i * G];
        float v;
        if (cnt > 0) v = h ? eS[i] * invZ : 0.f;
        else         v = uni;
        Bp[i * G] = v;
    }
}

// ---------------- k_syrk: wp = B^T B (symmetric) + fused GF = B^T R2 ----------------
// 560 blocks: 528 symmetric (bi>=bj) pairs + 32 V-panel blocks.
// f32x2 FFMA2 inner loop; A tile stored pre-splatted in smem.
#define TKS 16
__global__ __launch_bounds__(256, 2) void k_syrk() {
    int blk = blockIdx.x;
    int bi, bj; bool vpanel;
    if (blk < 528) {
        int l = blk; bi = 0;
        while (l > bi) { l -= (bi + 1); bi++; }
        bj = l; vpanel = false;
    } else {
        bi = blk - 528; bj = 0; vpanel = true;
    }
    int gi0 = bi * 128, gj0 = bj * 128;

    __shared__ float As2[TKS][256];   // splatted: col c -> (2c,2c+1)
    __shared__ float Bs[TKS][128];

    int tx = threadIdx.x & 15, ty = threadIdx.x >> 4;
    int lrow = threadIdx.x >> 5;          // 0..7
    int lc4 = (threadIdx.x & 31) * 4;     // 0..124

    unsigned long long acc[8][4];
    #pragma unroll
    for (int i = 0; i < 8; i++)
        #pragma unroll
        for (int j = 0; j < 4; j++) acc[i][j] = 0ull;

    float4 pA0, pA1, pB0, pB1;
    // prefetch tile 0
    pA0 = *(const float4*)&g_B[(0 + lrow) * G + gi0 + lc4];
    pA1 = *(const float4*)&g_B[(8 + lrow) * G + gi0 + lc4];
    if (!vpanel) {
        pB0 = *(const float4*)&g_B[(0 + lrow) * G + gj0 + lc4];
        pB1 = *(const float4*)&g_B[(8 + lrow) * G + gj0 + lc4];
    } else {
        pB0 = *(const float4*)&g_R2[(0 + lrow) * 128 + lc4];
        pB1 = *(const float4*)&g_R2[(8 + lrow) * 128 + lc4];
    }

    for (int k0 = 0; k0 < NT; k0 += TKS) {
        // store staged tile (A splatted)
        {
            ulonglong2 u;
            u.x = splat2(pA0.x); u.y = splat2(pA0.y);
            *(ulonglong2*)&As2[lrow][2 * lc4] = u;
            u.x = splat2(pA0.z); u.y = splat2(pA0.w);
            *(ulonglong2*)&As2[lrow][2 * lc4 + 4] = u;
            u.x = splat2(pA1.x); u.y = splat2(pA1.y);
            *(ulonglong2*)&As2[lrow + 8][2 * lc4] = u;
            u.x = splat2(pA1.z); u.y = splat2(pA1.w);
            *(ulonglong2*)&As2[lrow + 8][2 * lc4 + 4] = u;
            *(float4*)&Bs[lrow][lc4] = pB0;
            *(float4*)&Bs[lrow + 8][lc4] = pB1;
        }
        __syncthreads();
        // prefetch next tile
        int kn = k0 + TKS;
        if (kn < NT) {
            pA0 = *(const float4*)&g_B[(kn + lrow) * G + gi0 + lc4];
            pA1 = *(const float4*)&g_B[(kn + 8 + lrow) * G + gi0 + lc4];
            if (!vpanel) {
                pB0 = *(const float4*)&g_B[(kn + lrow) * G + gj0 + lc4];
                pB1 = *(const float4*)&g_B[(kn + 8 + lrow) * G + gj0 + lc4];
            } else {
                pB0 = *(const float4*)&g_R2[(kn + lrow) * 128 + lc4];
                pB1 = *(const float4*)&g_R2[(kn + 8 + lrow) * 128 + lc4];
            }
        }
        // compute
        #pragma unroll
        for (int kk = 0; kk < TKS; kk++) {
            const ulonglong2* ap = (const ulonglong2*)&As2[kk][ty * 16];
            ulonglong2 a01 = ap[0], a23 = ap[1], a45 = ap[2], a67 = ap[3];
            const ulonglong2* bp = (const ulonglong2*)&Bs[kk][tx * 8];
            ulonglong2 b01 = bp[0], b23 = bp[1];
            unsigned long long a[8] = {a01.x, a01.y, a23.x, a23.y, a45.x, a45.y, a67.x, a67.y};
            unsigned long long b[4] = {b01.x, b01.y, b23.x, b23.y};
            #pragma unroll
            for (int i = 0; i < 8; i++)
                #pragma unroll
                for (int j = 0; j < 4; j++)
                    fma2(acc[i][j], a[i], b[j]);
        }
        __syncthreads();
    }

    // epilogue
    #pragma unroll
    for (int i = 0; i < 8; i++) {
        float c[8];
        #pragma unroll
        for (int j = 0; j < 4; j++) unpack2(acc[i][j], c[2 * j], c[2 * j + 1]);
        int row = gi0 + ty * 8 + i;
        if (!vpanel) {
            int colb = gj0 + tx * 8;
            *(float4*)&g_wp[row * G + colb]     = make_float4(c[0], c[1], c[2], c[3]);
            *(float4*)&g_wp[row * G + colb + 4] = make_float4(c[4], c[5], c[6], c[7]);
            #pragma unroll
            for (int jj = 0; jj < 8; jj++)
                g_wp[(colb + jj) * G + row] = c[jj];
        } else {
            int colb = tx * 8;
            *(float4*)&g_GF[row * 128 + colb]     = make_float4(c[0], c[1], c[2], c[3]);
            *(float4*)&g_GF[row * 128 + colb + 4] = make_float4(c[4], c[5], c[6], c[7]);
        }
    }
}

// ---------------- k_norm ----------------
__global__ void k_norm() {
    int g = blockIdx.x * 256 + threadIdx.x;
    if (g < G) g_norm[g] = sqrtf(g_wp[g * G + g]);
}

// ---------------- k_msg: msg = A @ GF, deg = rowsum(A);  A = wp/(n_h n_g + eps) ----------------
__global__ void k_msg() {
    int h0 = blockIdx.x * 32;
    int tx = threadIdx.x & 15, ty = threadIdx.x >> 4;
    __shared__ float wpS[32][17];
    __shared__ float gfS[16][128];
    __shared__ float nS[16];
    float nh0 = g_norm[h0 + ty * 2];
    float nh1 = g_norm[h0 + ty * 2 + 1];
    float macc[2][8];
    #pragma unroll
    for (int i = 0; i < 2; i++)
        #pragma unroll
        for (int j = 0; j < 8; j++) macc[i][j] = 0.f;
    float dacc[2] = {0.f, 0.f};
    int lrow = threadIdx.x >> 5, lc4 = (threadIdx.x & 31) * 4;
    int wrow = threadIdx.x >> 3, wcol = (threadIdx.x & 7) * 2;

    for (int k0 = 0; k0 < G; k0 += 16) {
        float2 wv = *(const float2*)&g_wp[(h0 + wrow) * G + k0 + wcol];
        wpS[wrow][wcol] = wv.x;
        wpS[wrow][wcol + 1] = wv.y;
        *(float4*)&gfS[lrow][lc4]     = *(const float4*)&g_GF[(k0 + lrow) * 128 + lc4];
        *(float4*)&gfS[lrow + 8][lc4] = *(const float4*)&g_GF[(k0 + lrow + 8) * 128 + lc4];
        if (threadIdx.x < 16) nS[threadIdx.x] = g_norm[k0 + threadIdx.x];
        __syncthreads();
        #pragma unroll
        for (int kk = 0; kk < 16; kk++) {
            float ng = nS[kk];
            float a0 = __fdividef(wpS[ty * 2][kk],     nh0 * ng + EPSL);
            float a1 = __fdividef(wpS[ty * 2 + 1][kk], nh1 * ng + EPSL);
            dacc[0] += a0; dacc[1] += a1;
            #pragma unroll
            for (int j = 0; j < 8; j++) {
                float b = gfS[kk][tx * 8 + j];
                macc[0][j] += a0 * b;
                macc[1][j] += a1 * b;
            }
        }
        __syncthreads();
    }
    #pragma unroll
    for (int ii = 0; ii < 2; ii++) {
        int h = h0 + ty * 2 + ii;
        #pragma unroll
        for (int j = 0; j < 8; j++) g_msg[h * 128 + tx * 8 + j] = macc[ii][j];
        if (tx == 0) g_deg[h] = dacc[ii];
    }
}

// ---------------- k_out: agg = a*GF + (1-a)*msg/deg ; out = sigmoid(agg @ gW^T + gb) ----------------
__global__ void k_out(const float* __restrict__ gW, const float* __restrict__ gb,
                      float* __restrict__ out) {
    int g = blockIdx.x;
    int t = threadIdx.x;
    __shared__ float aggS[128];
    float dg = g_deg[g];
    float invd = (dg > 0.f) ? 1.f / dg : 0.f;
    for (int c = t; c < 128; c += 64) {
        float hn = g_msg[g * 128 + c] * invd;
        aggS[c] = ALPHA * g_GF[g * 128 + c] + (1.f - ALPHA) * hn;
    }
    __syncthreads();
    float acc = gb[t];
    #pragma unroll
    for (int c = 0; c < 128; c++) acc += aggS[c] * gW[t * 128 + c];
    out[g * OD + t] = 1.f / (1.f + expf(-acc));
}

// ---------------- launch ----------------
extern "C" void kernel_launch(void* const* d_in, const int* in_sizes, int n_in,
                              void* d_out, int out_size) {
    // num_groups may or may not be present as a size-1 input at index 2
    int base = (in_sizes[2] == 1) ? 3 : 2;
    const int*   H   = (const int*)d_in[0];
    const float* X   = (const float*)d_in[1];
    const float* uWq = (const float*)d_in[base + 0];
    const float* ubq = (const float*)d_in[base + 1];
    const float* uWk = (const float*)d_in[base + 2];
    const float* ubk = (const float*)d_in[base + 3];
    const float* uWv = (const float*)d_in[base + 4];
    const float* ubv = (const float*)d_in[base + 5];
    const float* uWs = (const float*)d_in[base + 6];
    const float* ubs = (const float*)d_in[base + 7];
    const float* iWq = (const float*)d_in[base + 8];
    const float* ibq = (const float*)d_in[base + 9];
    const float* iWk = (const float*)d_in[base + 10];
    const float* ibk = (const float*)d_in[base + 11];
    const float* iWv = (const float*)d_in[base + 12];
    const float* ibv = (const float*)d_in[base + 13];
    const float* iWs = (const float*)d_in[base + 14];
    const float* ibs = (const float*)d_in[base + 15];
    const float* gW  = (const float*)d_in[base + 16];
    const float* gb  = (const float*)d_in[base + 17];
    float* out = (float*)d_out;

    k_zero<<<32, 256>>>();
    k_reduce<<<dim3(20, 2), 256>>>(X, uWs, iWs);
    k_prep<<<1, 64>>>(uWk, ubk, uWq, ubq, ubs, iWk, ibk, iWq, ibq, ibs);
    k_ev<<<NT, 64>>>(X, uWv, ubv, iWv, ibv);
    k_z<<<dim3(16, 18), 256>>>(H);
    k_b<<<dim3(16, 18), 256>>>(H);
    k_syrk<<<560, 256>>>();
    k_norm<<<16, 256>>>();
    k_msg<<<128, 256>>>();
    k_out<<<G, 64>>>(gW, gb, out);
}

// round 10
// speedup vs baseline: 1.0036x; 1.0036x over previous
#include <cuda_runtime.h>

// ---------------- problem constants ----------------
#define NU 8000
#define NI 10000
#define NT 18000
#define G  4096
#define D  64
#define HD 64
#define OD 64
#define ALPHA 0.8f
#define EPSL  1e-8f

// ---------------- scratch (device globals; no allocation allowed) ----------------
__device__ float g_B[NT * G];        // group_weights^T  (18000 x 4096)  ~295 MB
__device__ float g_R2[NT * 128];     // [V_u | 0 ; 0 | V_i]              ~9.2 MB
__device__ float g_V[NT * HD];       // v projections
__device__ float g_E[NT];            // exp(s)
__device__ float g_Z[2 * G];         // per-half softmax denominators
__device__ int   g_cnt[2 * G];       // per-half unmasked counts
__device__ float g_wp[G * G];        // B^T B                           ~67 MB
__device__ float g_GF[G * 128];      // group_feats
__device__ float g_msg[G * 128];
__device__ float g_deg[G];
__device__ float g_norm[G];
__device__ float g_red[2 * 65];      // [r(64) | sum Ws] per half
__device__ float g_uvec[2 * D];
__device__ float g_ccon[2];

// ---------------- f32x2 helpers ----------------
__device__ __forceinline__ unsigned long long splat2(float x) {
    unsigned long long r;
    asm("mov.b64 %0, {%1, %1};" : "=l"(r) : "f"(x));
    return r;
}
__device__ __forceinline__ void fma2(unsigned long long& d, unsigned long long a, unsigned long long b) {
    asm("fma.rn.f32x2 %0, %1, %2, %0;" : "+l"(d) : "l"(a), "l"(b));
}
__device__ __forceinline__ void unpack2(unsigned long long v, float& lo, float& hi) {
    asm("mov.b64 {%0, %1}, %2;" : "=f"(lo), "=f"(hi) : "l"(v));
}

// ---------------- k_zero: clear accumulators ----------------
__global__ void k_zero() {
    int i = blockIdx.x * blockDim.x + threadIdx.x;
    if (i < 2 * 65) g_red[i] = 0.f;
    if (i < 2 * G) { g_Z[i] = 0.f; g_cnt[i] = 0; }
}

// ---------------- k_reduce: r = sum_m Ws[m] * x[m,:],  sw = sum Ws ----------------
__global__ void k_reduce(const float* __restrict__ x,
                         const float* __restrict__ uWs,
                         const float* __restrict__ iWs) {
    int half = blockIdx.y;
    int m0 = blockIdx.x * 500;
    int Nh = half ? NI : NU;
    if (m0 >= Nh) return;
    const float* Ws = half ? iWs : uWs;
    int off = half ? NU : 0;
    int md = threadIdx.x >> 6;   // 0..3
    int dd = threadIdx.x & 63;
    float acc = 0.f, sw = 0.f;
    int m1 = min(m0 + 500, Nh);
    for (int m = m0 + md; m < m1; m += 4) {
        float w = Ws[m];
        acc += w * x[(off + m) * D + dd];
        if (dd == 0) sw += w;
    }
    __shared__ float sA[4][64];
    __shared__ float sW[4];
    sA[md][dd] = acc;
    if (dd == 0) sW[md] = sw;
    __syncthreads();
    if (md == 0) {
        float t = sA[0][dd] + sA[1][dd] + sA[2][dd] + sA[3][dd];
        atomicAdd(&g_red[half * 65 + dd], t);
        if (dd == 0) atomicAdd(&g_red[half * 65 + 64], sW[0] + sW[1] + sW[2] + sW[3]);
    }
}

// ---------------- k_prep: t = Wk r + sw*bk ; uvec = Wq^T t ; c = bq.t + bs ----------------
__global__ void k_prep(const float* __restrict__ uWk, const float* __restrict__ ubk,
                       const float* __restrict__ uWq, const float* __restrict__ ubq,
                       const float* __restrict__ ubs,
                       const float* __restrict__ iWk, const float* __restrict__ ibk,
                       const float* __restrict__ iWq, const float* __restrict__ ibq,
                       const float* __restrict__ ibs) {
    __shared__ float rS[64], tS[64];
    int t = threadIdx.x;
    for (int half = 0; half < 2; half++) {
        const float* Wk = half ? iWk : uWk; const float* bk = half ? ibk : ubk;
        const float* Wq = half ? iWq : uWq; const float* bq = half ? ibq : ubq;
        const float* bs = half ? ibs : ubs;
        rS[t] = g_red[half * 65 + t];
        __syncthreads();
        float sw = g_red[half * 65 + 64];
        float tv = 0.f;
        for (int d = 0; d < D; d++) tv += Wk[t * D + d] * rS[d];
        tv += sw * bk[t];
        tS[t] = tv;
        __syncthreads();
        float u = 0.f;
        for (int hd = 0; hd < HD; hd++) u += Wq[hd * D + t] * tS[hd];
        g_uvec[half * 64 + t] = u;
        if (t == 0) {
            float c = bs[0];
            for (int hd = 0; hd < HD; hd++) c += bq[hd] * tS[hd];
            g_ccon[half] = c;
        }
        __syncthreads();
    }
}

// ---------------- k_ev: per-row E[n]=exp(s[n]), V row, R2 row ----------------
__global__ void k_ev(const float* __restrict__ x,
                     const float* __restrict__ uWv, const float* __restrict__ ubv,
                     const float* __restrict__ iWv, const float* __restrict__ ibv) {
    int n = blockIdx.x;
    int half = (n >= NU) ? 1 : 0;
    const float* Wv = half ? iWv : uWv;
    const float* bv = half ? ibv : ubv;
    __shared__ float xs[64];
    __shared__ float ps[64];
    int t = threadIdx.x;
    xs[t] = x[n * D + t];
    __syncthreads();
    float v = bv[t];
    #pragma unroll
    for (int d = 0; d < D; d++) v += Wv[t * D + d] * xs[d];
    g_V[n * HD + t] = v;
    if (half == 0) { g_R2[n * 128 + t] = v;   g_R2[n * 128 + 64 + t] = 0.f; }
    else           { g_R2[n * 128 + t] = 0.f; g_R2[n * 128 + 64 + t] = v;  }
    ps[t] = xs[t] * g_uvec[half * 64 + t];
    __syncthreads();
    if (t < 32) ps[t] += ps[t + 32];
    __syncwarp();
    if (t == 0) {
        float s = 0.f;
        #pragma unroll
        for (int i = 0; i < 32; i++) s += ps[i];
        g_E[n] = expf(s + g_ccon[half]);
    }
}

// ---------------- k_z: Z_g and counts per half ----------------
__global__ void k_z(const int* __restrict__ H) {
    int gcol = blockIdx.x * 256 + threadIdx.x;
    int n0 = blockIdx.y * 1000;
    int half = (n0 >= NU) ? 1 : 0;
    __shared__ float eS[1000];
    for (int i = threadIdx.x; i < 1000; i += 256) eS[i] = g_E[n0 + i];
    __syncthreads();
    float z = 0.f; int c = 0;
    const int* Hp = H + n0 * G + gcol;
    for (int i = 0; i < 1000; i++) {
        if (Hp[i * G] != 0) { z += eS[i]; c++; }
    }
    atomicAdd(&g_Z[half * G + gcol], z);
    atomicAdd(&g_cnt[half * G + gcol], c);
}

// ---------------- k_b: build B[n,g] = softmax weight (transposed) ----------------
__global__ void k_b(const int* __restrict__ H) {
    int gcol = blockIdx.x * 256 + threadIdx.x;
    int n0 = blockIdx.y * 1000;
    int half = (n0 >= NU) ? 1 : 0;
    __shared__ float eS[1000];
    for (int i = threadIdx.x; i < 1000; i += 256) eS[i] = g_E[n0 + i];
    __syncthreads();
    int cnt = g_cnt[half * G + gcol];
    float invZ = (cnt > 0) ? 1.f / g_Z[half * G + gcol] : 0.f;
    float uni = 1.f / (half ? (float)NI : (float)NU);
    const int* Hp = H + n0 * G + gcol;
    float* Bp = g_B + n0 * G + gcol;
    for (int i = 0; i < 1000; i++) {
        int h = Hp[i * G];
        float v;
        if (cnt > 0) v = h ? eS[i] * invZ : 0.f;
        else         v = uni;
        Bp[i * G] = v;
    }
}

// ---------------- k_syrk: wp = B^T B (symmetric) + fused GF = B^T R2 ----------------
// 560 blocks: 528 symmetric (bi>=bj) pairs + 32 V-panel blocks.
// f32x2 FFMA2 inner loop; A tile stored pre-splatted in smem.
#define TKS 16
__global__ __launch_bounds__(256, 2) void k_syrk() {
    int blk = blockIdx.x;
    int bi, bj; bool vpanel;
    if (blk < 528) {
        int l = blk; bi = 0;
        while (l > bi) { l -= (bi + 1); bi++; }
        bj = l; vpanel = false;
    } else {
        bi = blk - 528; bj = 0; vpanel = true;
    }
    int gi0 = bi * 128, gj0 = bj * 128;

    __shared__ float As2[TKS][256];   // splatted: col c -> (2c,2c+1)
    __shared__ float Bs[TKS][128];

    int tx = threadIdx.x & 15, ty = threadIdx.x >> 4;
    int lrow = threadIdx.x >> 5;          // 0..7
    int lc4 = (threadIdx.x & 31) * 4;     // 0..124

    unsigned long long acc[8][4];
    #pragma unroll
    for (int i = 0; i < 8; i++)
        #pragma unroll
        for (int j = 0; j < 4; j++) acc[i][j] = 0ull;

    float4 pA0, pA1, pB0, pB1;
    // prefetch tile 0
    pA0 = *(const float4*)&g_B[(0 + lrow) * G + gi0 + lc4];
    pA1 = *(const float4*)&g_B[(8 + lrow) * G + gi0 + lc4];
    if (!vpanel) {
        pB0 = *(const float4*)&g_B[(0 + lrow) * G + gj0 + lc4];
        pB1 = *(const float4*)&g_B[(8 + lrow) * G + gj0 + lc4];
    } else {
        pB0 = *(const float4*)&g_R2[(0 + lrow) * 128 + lc4];
        pB1 = *(const float4*)&g_R2[(8 + lrow) * 128 + lc4];
    }

    for (int k0 = 0; k0 < NT; k0 += TKS) {
        // store staged tile (A splatted)
        {
            ulonglong2 u;
            u.x = splat2(pA0.x); u.y = splat2(pA0.y);
            *(ulonglong2*)&As2[lrow][2 * lc4] = u;
            u.x = splat2(pA0.z); u.y = splat2(pA0.w);
            *(ulonglong2*)&As2[lrow][2 * lc4 + 4] = u;
            u.x = splat2(pA1.x); u.y = splat2(pA1.y);
            *(ulonglong2*)&As2[lrow + 8][2 * lc4] = u;
            u.x = splat2(pA1.z); u.y = splat2(pA1.w);
            *(ulonglong2*)&As2[lrow + 8][2 * lc4 + 4] = u;
            *(float4*)&Bs[lrow][lc4] = pB0;
            *(float4*)&Bs[lrow + 8][lc4] = pB1;
        }
        __syncthreads();
        // prefetch next tile
        int kn = k0 + TKS;
        if (kn < NT) {
            pA0 = *(const float4*)&g_B[(kn + lrow) * G + gi0 + lc4];
            pA1 = *(const float4*)&g_B[(kn + 8 + lrow) * G + gi0 + lc4];
            if (!vpanel) {
                pB0 = *(const float4*)&g_B[(kn + lrow) * G + gj0 + lc4];
                pB1 = *(const float4*)&g_B[(kn + 8 + lrow) * G + gj0 + lc4];
            } else {
                pB0 = *(const float4*)&g_R2[(kn + lrow) * 128 + lc4];
                pB1 = *(const float4*)&g_R2[(kn + 8 + lrow) * 128 + lc4];
            }
        }
        // compute
        #pragma unroll
        for (int kk = 0; kk < TKS; kk++) {
            const ulonglong2* ap = (const ulonglong2*)&As2[kk][ty * 16];
            ulonglong2 a01 = ap[0], a23 = ap[1], a45 = ap[2], a67 = ap[3];
            const ulonglong2* bp = (const ulonglong2*)&Bs[kk][tx * 8];
            ulonglong2 b01 = bp[0], b23 = bp[1];
            unsigned long long a[8] = {a01.x, a01.y, a23.x, a23.y, a45.x, a45.y, a67.x, a67.y};
            unsigned long long b[4] = {b01.x, b01.y, b23.x, b23.y};
            #pragma unroll
            for (int i = 0; i < 8; i++)
                #pragma unroll
                for (int j = 0; j < 4; j++)
                    fma2(acc[i][j], a[i], b[j]);
        }
        __syncthreads();
    }

    // epilogue
    #pragma unroll
    for (int i = 0; i < 8; i++) {
        float c[8];
        #pragma unroll
        for (int j = 0; j < 4; j++) unpack2(acc[i][j], c[2 * j], c[2 * j + 1]);
        int row = gi0 + ty * 8 + i;
        if (!vpanel) {
            int colb = gj0 + tx * 8;
            *(float4*)&g_wp[row * G + colb]     = make_float4(c[0], c[1], c[2], c[3]);
            *(float4*)&g_wp[row * G + colb + 4] = make_float4(c[4], c[5], c[6], c[7]);
            #pragma unroll
            for (int jj = 0; jj < 8; jj++)
                g_wp[(colb + jj) * G + row] = c[jj];
        } else {
            int colb = tx * 8;
            *(float4*)&g_GF[row * 128 + colb]     = make_float4(c[0], c[1], c[2], c[3]);
            *(float4*)&g_GF[row * 128 + colb + 4] = make_float4(c[4], c[5], c[6], c[7]);
        }
    }
}

// ---------------- k_norm ----------------
__global__ void k_norm() {
    int g = blockIdx.x * 256 + threadIdx.x;
    if (g < G) g_norm[g] = sqrtf(g_wp[g * G + g]);
}

// ---------------- k_msg: msg = A @ GF, deg = rowsum(A);  A = wp/(n_h n_g + eps) ----------------
__global__ void k_msg() {
    int h0 = blockIdx.x * 32;
    int tx = threadIdx.x & 15, ty = threadIdx.x >> 4;
    __shared__ float wpS[32][17];
    __shared__ float gfS[16][128];
    __shared__ float nS[16];
    float nh0 = g_norm[h0 + ty * 2];
    float nh1 = g_norm[h0 + ty * 2 + 1];
    float macc[2][8];
    #pragma unroll
    for (int i = 0; i < 2; i++)
        #pragma unroll
        for (int j = 0; j < 8; j++) macc[i][j] = 0.f;
    float dacc[2] = {0.f, 0.f};
    int lrow = threadIdx.x >> 5, lc4 = (threadIdx.x & 31) * 4;
    int wrow = threadIdx.x >> 3, wcol = (threadIdx.x & 7) * 2;

    for (int k0 = 0; k0 < G; k0 += 16) {
        float2 wv = *(const float2*)&g_wp[(h0 + wrow) * G + k0 + wcol];
        wpS[wrow][wcol] = wv.x;
        wpS[wrow][wcol + 1] = wv.y;
        *(float4*)&gfS[lrow][lc4]     = *(const float4*)&g_GF[(k0 + lrow) * 128 + lc4];
        *(float4*)&gfS[lrow + 8][lc4] = *(const float4*)&g_GF[(k0 + lrow + 8) * 128 + lc4];
        if (threadIdx.x < 16) nS[threadIdx.x] = g_norm[k0 + threadIdx.x];
        __syncthreads();
        #pragma unroll
        for (int kk = 0; kk < 16; kk++) {
            float ng = nS[kk];
            float a0 = __fdividef(wpS[ty * 2][kk],     nh0 * ng + EPSL);
            float a1 = __fdividef(wpS[ty * 2 + 1][kk], nh1 * ng + EPSL);
            dacc[0] += a0; dacc[1] += a1;
            #pragma unroll
            for (int j = 0; j < 8; j++) {
                float b = gfS[kk][tx * 8 + j];
                macc[0][j] += a0 * b;
                macc[1][j] += a1 * b;
            }
        }
        __syncthreads();
    }
    #pragma unroll
    for (int ii = 0; ii < 2; ii++) {
        int h = h0 + ty * 2 + ii;
        #pragma unroll
        for (int j = 0; j < 8; j++) g_msg[h * 128 + tx * 8 + j] = macc[ii][j];
        if (tx == 0) g_deg[h] = dacc[ii];
    }
}

// ---------------- k_out: agg = a*GF + (1-a)*msg/deg ; out = sigmoid(agg @ gW^T + gb) ----------------
__global__ void k_out(const float* __restrict__ gW, const float* __restrict__ gb,
                      float* __restrict__ out) {
    int g = blockIdx.x;
    int t = threadIdx.x;
    __shared__ float aggS[128];
    float dg = g_deg[g];
    float invd = (dg > 0.f) ? 1.f / dg : 0.f;
    for (int c = t; c < 128; c += 64) {
        float hn = g_msg[g * 128 + c] * invd;
        aggS[c] = ALPHA * g_GF[g * 128 + c] + (1.f - ALPHA) * hn;
    }
    __syncthreads();
    float acc = gb[t];
    #pragma unroll
    for (int c = 0; c < 128; c++) acc += aggS[c] * gW[t * 128 + c];
    out[g * OD + t] = 1.f / (1.f + expf(-acc));
}

// ---------------- launch ----------------
extern "C" void kernel_launch(void* const* d_in, const int* in_sizes, int n_in,
                              void* d_out, int out_size) {
    // num_groups may or may not be present as a size-1 input at index 2
    int base = (in_sizes[2] == 1) ? 3 : 2;
    const int*   H   = (const int*)d_in[0];
    const float* X   = (const float*)d_in[1];
    const float* uWq = (const float*)d_in[base + 0];
    const float* ubq = (const float*)d_in[base + 1];
    const float* uWk = (const float*)d_in[base + 2];
    const float* ubk = (const float*)d_in[base + 3];
    const float* uWv = (const float*)d_in[base + 4];
    const float* ubv = (const float*)d_in[base + 5];
    const float* uWs = (const float*)d_in[base + 6];
    const float* ubs = (const float*)d_in[base + 7];
    const float* iWq = (const float*)d_in[base + 8];
    const float* ibq = (const float*)d_in[base + 9];
    const float* iWk = (const float*)d_in[base + 10];
    const float* ibk = (const float*)d_in[base + 11];
    const float* iWv = (const float*)d_in[base + 12];
    const float* ibv = (const float*)d_in[base + 13];
    const float* iWs = (const float*)d_in[base + 14];
    const float* ibs = (const float*)d_in[base + 15];
    const float* gW  = (const float*)d_in[base + 16];
    const float* gb  = (const float*)d_in[base + 17];
    float* out = (float*)d_out;

    k_zero<<<32, 256>>>();
    k_reduce<<<dim3(20, 2), 256>>>(X, uWs, iWs);
    k_prep<<<1, 64>>>(uWk, ubk, uWq, ubq, ubs, iWk, ibk, iWq, ibq, ibs);
    k_ev<<<NT, 64>>>(X, uWv, ubv, iWv, ibv);
    k_z<<<dim3(16, 18), 256>>>(H);
    k_b<<<dim3(16, 18), 256>>>(H);
    k_syrk<<<560, 256>>>();
    k_norm<<<16, 256>>>();
    k_msg<<<128, 256>>>();
    k_out<<<G, 64>>>(gW, gb, out);
}

// round 12
// speedup vs baseline: 2.9948x; 2.9840x over previous
#include <cuda_runtime.h>
#include <cuda_bf16.h>
#include <cstdint>

// ---------------- problem constants ----------------
#define NU 8000
#define NI 10000
#define NT 18000
#define G  4096
#define KPU 8064          // u-half padded rows (126*64)
#define KP  18112         // total padded K
#define ALPHA 0.8f
#define EPSL  1e-8f
#define INV_NU (1.0f/8000.0f)
#define INV_NI (1.0f/10000.0f)

// k_mma tiling
#define KC 32
#define NSTEP 566         // KP/KC
#define STEP_U 252        // KPU/KC
#define MAT_SZ 8192       // 128 rows * 64 B
#define STG    24576      // 3 mats
#define SMEM_MMA 73728    // 3 stages

// ---------------- device scratch ----------------
__device__ __align__(256) __nv_bfloat16 g_Ahi[(size_t)G * KP]; // m*E^2 hi
__device__ __align__(256) __nv_bfloat16 g_Alo[(size_t)G * KP]; // m*E^2 lo
__device__ __align__(256) __nv_bfloat16 g_M  [(size_t)G * KP]; // binary mask
__device__ __align__(256) __nv_bfloat16 g_Whi[(size_t)128 * KP]; // E*V hi (transposed, zero-padded per half)
__device__ __align__(256) __nv_bfloat16 g_Wlo[(size_t)128 * KP];
__device__ __align__(256) float g_V[(size_t)NT * 64];
__device__ float g_E[NT];
__device__ float g_Z[2 * G];
__device__ int   g_cnt[2 * G];
__device__ float g_iZ[2 * G];
__device__ int   g_degf[2 * G];
__device__ float g_csV[128];
__device__ __align__(256) float g_wp[(size_t)G * G];
__device__ __align__(256) float g_GF[G * 128];
__device__ float g_msg[G * 128];
__device__ float g_deg[G];
__device__ float g_norm[G];
__device__ float g_red[2 * 65];
__device__ float g_uvec[2 * 64];
__device__ float g_ccon[2];

// ---------------- PTX helpers (base compute_103 — no 'a'-features) ----------------
__device__ __forceinline__ uint32_t smem_u32(const void* p) {
    uint32_t a;
    asm("{ .reg .u64 t; cvta.to.shared.u64 t, %1; cvt.u32.u64 %0, t; }" : "=r"(a) : "l"(p));
    return a;
}
__device__ __forceinline__ void cpasync16(uint32_t dst, const void* src) {
    asm volatile("cp.async.cg.shared.global [%0], [%1], 16;" :: "r"(dst), "l"(src) : "memory");
}
#define CP_COMMIT() asm volatile("cp.async.commit_group;" ::: "memory")
#define CP_WAIT1()  asm volatile("cp.async.wait_group 1;" ::: "memory")

__device__ __forceinline__ void ldsm4(uint32_t& r0, uint32_t& r1, uint32_t& r2, uint32_t& r3,
                                      uint32_t addr) {
    asm volatile("ldmatrix.sync.aligned.m8n8.x4.shared.b16 {%0,%1,%2,%3}, [%4];"
                 : "=r"(r0), "=r"(r1), "=r"(r2), "=r"(r3) : "r"(addr));
}
__device__ __forceinline__ void mma16816(float* c, const uint32_t* a, const uint32_t* b) {
    asm volatile(
        "mma.sync.aligned.m16n8k16.row.col.f32.bf16.bf16.f32 "
        "{%0,%1,%2,%3}, {%4,%5,%6,%7}, {%8,%9}, {%0,%1,%2,%3};"
        : "+f"(c[0]), "+f"(c[1]), "+f"(c[2]), "+f"(c[3])
        : "r"(a[0]), "r"(a[1]), "r"(a[2]), "r"(a[3]), "r"(b[0]), "r"(b[1]));
}

// ---------------- k_zero ----------------
__global__ void k_zero() {
    int i = blockIdx.x * blockDim.x + threadIdx.x;
    if (i < 2 * 65) g_red[i] = 0.f;
    if (i < 2 * G) { g_Z[i] = 0.f; g_cnt[i] = 0; }
}

// ---------------- k_reduce: r = sum_m Ws[m] x[m,:], sw = sum Ws ----------------
__global__ void k_reduce(const float* __restrict__ x,
                         const float* __restrict__ uWs,
                         const float* __restrict__ iWs) {
    int half = blockIdx.y;
    int m0 = blockIdx.x * 500;
    int Nh = half ? NI : NU;
    if (m0 >= Nh) return;
    const float* Ws = half ? iWs : uWs;
    int off = half ? NU : 0;
    int md = threadIdx.x >> 6;
    int dd = threadIdx.x & 63;
    float acc = 0.f, sw = 0.f;
    int m1 = min(m0 + 500, Nh);
    for (int m = m0 + md; m < m1; m += 4) {
        float w = Ws[m];
        acc += w * x[(size_t)(off + m) * 64 + dd];
        if (dd == 0) sw += w;
    }
    __shared__ float sA[4][64];
    __shared__ float sW[4];
    sA[md][dd] = acc;
    if (dd == 0) sW[md] = sw;
    __syncthreads();
    if (md == 0) {
        float t = sA[0][dd] + sA[1][dd] + sA[2][dd] + sA[3][dd];
        atomicAdd(&g_red[half * 65 + dd], t);
        if (dd == 0) atomicAdd(&g_red[half * 65 + 64], sW[0] + sW[1] + sW[2] + sW[3]);
    }
}

// ---------------- k_prep ----------------
__global__ void k_prep(const float* __restrict__ uWk, const float* __restrict__ ubk,
                       const float* __restrict__ uWq, const float* __restrict__ ubq,
                       const float* __restrict__ ubs,
                       const float* __restrict__ iWk, const float* __restrict__ ibk,
                       const float* __restrict__ iWq, const float* __restrict__ ibq,
                       const float* __restrict__ ibs) {
    __shared__ float rS[64], tS[64];
    int t = threadIdx.x;
    for (int half = 0; half < 2; half++) {
        const float* Wk = half ? iWk : uWk; const float* bk = half ? ibk : ubk;
        const float* Wq = half ? iWq : uWq; const float* bq = half ? ibq : ubq;
        const float* bs = half ? ibs : ubs;
        rS[t] = g_red[half * 65 + t];
        __syncthreads();
        float sw = g_red[half * 65 + 64];
        float tv = 0.f;
        for (int d = 0; d < 64; d++) tv += Wk[t * 64 + d] * rS[d];
        tv += sw * bk[t];
        tS[t] = tv;
        __syncthreads();
        float u = 0.f;
        for (int hd = 0; hd < 64; hd++) u += Wq[hd * 64 + t] * tS[hd];
        g_uvec[half * 64 + t] = u;
        if (t == 0) {
            float c = bs[0];
            for (int hd = 0; hd < 64; hd++) c += bq[hd] * tS[hd];
            g_ccon[half] = c;
        }
        __syncthreads();
    }
}

// ---------------- k_ev: V rows + E=exp(s) (32 rows per block) ----------------
__global__ __launch_bounds__(256) void k_ev(const float* __restrict__ x,
                     const float* __restrict__ uWv, const float* __restrict__ ubv,
                     const float* __restrict__ iWv, const float* __restrict__ ibv) {
    int r0 = blockIdx.x * 32;
    int half = (r0 >= NU) ? 1 : 0;
    const float* Wv = half ? iWv : uWv;
    const float* bv = half ? ibv : ubv;
    __shared__ float wS[64][65];
    __shared__ float xS[32][65];
    __shared__ float bS[64], uS[64];
    int tid = threadIdx.x;
    for (int i = tid; i < 4096; i += 256) wS[i >> 6][i & 63] = Wv[i];
    if (tid < 64) { bS[tid] = bv[tid]; uS[tid] = g_uvec[half * 64 + tid]; }
    for (int i = tid; i < 2048; i += 256) {
        int rr = i >> 6;
        int gr = r0 + rr;
        xS[rr][i & 63] = (gr < NT) ? x[(size_t)gr * 64 + (i & 63)] : 0.f;
    }
    __syncthreads();
    int row = tid >> 3;
    int c0 = (tid & 7) * 8;
    float v[8];
    #pragma unroll
    for (int j = 0; j < 8; j++) v[j] = bS[c0 + j];
    #pragma unroll 8
    for (int d = 0; d < 64; d++) {
        float xv = xS[row][d];
        #pragma unroll
        for (int j = 0; j < 8; j++) v[j] += wS[c0 + j][d] * xv;
    }
    int gr = r0 + row;
    if (gr < NT) {
        #pragma unroll
        for (int j = 0; j < 8; j++) g_V[(size_t)gr * 64 + c0 + j] = v[j];
    }
    float p = 0.f;
    #pragma unroll
    for (int j = 0; j < 8; j++) p += xS[row][c0 + j] * uS[c0 + j];
    p += __shfl_xor_sync(0xffffffff, p, 1);
    p += __shfl_xor_sync(0xffffffff, p, 2);
    p += __shfl_xor_sync(0xffffffff, p, 4);
    if ((tid & 7) == 0 && gr < NT) g_E[gr] = expf(p + g_ccon[half]);
}

// ---------------- k_z: Z_g and counts per half ----------------
__global__ void k_z(const int* __restrict__ H) {
    int gcol = blockIdx.x * 256 + threadIdx.x;
    int n0 = blockIdx.y * 1000;
    int half = (n0 >= NU) ? 1 : 0;
    __shared__ float eS[1000];
    for (int i = threadIdx.x; i < 1000; i += 256) eS[i] = g_E[n0 + i];
    __syncthreads();
    float z = 0.f; int c = 0;
    const int* Hp = H + (size_t)n0 * G + gcol;
    for (int i = 0; i < 1000; i++) {
        if (Hp[(size_t)i * G] != 0) { z += eS[i]; c++; }
    }
    atomicAdd(&g_Z[half * G + gcol], z);
    atomicAdd(&g_cnt[half * G + gcol], c);
}

// ---------------- k_inv ----------------
__global__ void k_inv() {
    int i = blockIdx.x * 256 + threadIdx.x;
    if (i < 2 * G) {
        int c = g_cnt[i];
        g_iZ[i] = (c > 0) ? 1.f / g_Z[i] : 0.f;
        g_degf[i] = (c == 0) ? 1 : 0;
    }
}

// ---------------- k_pack: Ahi/Alo = split(m*E^2), M = m (K-major panels) ----------------
__global__ __launch_bounds__(256) void k_pack(const int* __restrict__ H) {
    int g0 = blockIdx.x * 128;
    int n0 = blockIdx.y * 64;
    bool half_i = (n0 >= KPU);
    __shared__ float e2s[64];
    __shared__ int gns[64];
    int tid = threadIdx.x;
    if (tid < 64) {
        int n = n0 + tid;
        int gn;
        if (!half_i) gn = (n < NU) ? n : -1;
        else { int k = n - KPU; gn = (k < NI) ? (NU + k) : -1; }
        gns[tid] = gn;
        float e = (gn >= 0) ? g_E[gn] : 0.f;
        e2s[tid] = e * e;
    }
    __syncthreads();
    int gl = tid & 127;
    int g = g0 + gl;
    bool dead = (g_cnt[(half_i ? G : 0) + g] == 0);
    int cgrp = tid >> 7;
    union U8 { __nv_bfloat16 h[8]; uint4 v; };
    for (int q = 0; q < 4; q++) {
        int ck = cgrp * 4 + q;
        U8 uh, ul, um;
        #pragma unroll
        for (int j = 0; j < 8; j++) {
            int nl = ck * 8 + j;
            int gn = gns[nl];
            float a = 0.f;
            float mv = 0.f;
            if (gn >= 0 && !dead) {
                int h = H[(size_t)gn * G + g];
                if (h != 0) { a = e2s[nl]; mv = 1.f; }
            }
            __nv_bfloat16 ah = __float2bfloat16(a);
            uh.h[j] = ah;
            ul.h[j] = __float2bfloat16(a - __bfloat162float(ah));
            um.h[j] = __float2bfloat16(mv);
        }
        size_t off = (size_t)g * KP + n0 + ck * 8;
        *(uint4*)&g_Ahi[off] = uh.v;
        *(uint4*)&g_Alo[off] = ul.v;
        *(uint4*)&g_M[off]   = um.v;
    }
}

// ---------------- k_w: Whi/Wlo[c][n] = split(E[n]*R2[n][c]) ----------------
__global__ __launch_bounds__(256) void k_w() {
    int n0 = blockIdx.x * 64;
    bool half_i = (n0 >= KPU);
    __shared__ float es[64];
    __shared__ int gns[64];
    int tid = threadIdx.x;
    if (tid < 64) {
        int n = n0 + tid;
        int gn;
        if (!half_i) gn = (n < NU) ? n : -1;
        else { int k = n - KPU; gn = (k < NI) ? (NU + k) : -1; }
        gns[tid] = gn;
        es[tid] = (gn >= 0) ? g_E[gn] : 0.f;
    }
    __syncthreads();
    int c = tid & 127;
    int cgrp = tid >> 7;
    bool active = half_i ? (c >= 64) : (c < 64);
    int vc = half_i ? (c - 64) : c;
    union U8 { __nv_bfloat16 h[8]; uint4 v; };
    for (int q = 0; q < 4; q++) {
        int ck = cgrp * 4 + q;
        U8 uh, ul;
        #pragma unroll
        for (int j = 0; j < 8; j++) {
            int nl = ck * 8 + j;
            int gn = gns[nl];
            float w = 0.f;
            if (active && gn >= 0) w = es[nl] * g_V[(size_t)gn * 64 + vc];
            __nv_bfloat16 wh = __float2bfloat16(w);
            uh.h[j] = wh;
            ul.h[j] = __float2bfloat16(w - __bfloat162float(wh));
        }
        size_t off = (size_t)c * KP + n0 + ck * 8;
        *(uint4*)&g_Whi[off] = uh.v;
        *(uint4*)&g_Wlo[off] = ul.v;
    }
}

// ---------------- k_csv: column sums of V per half ----------------
__global__ void k_csv() {
    int half = blockIdx.x;
    int c = threadIdx.x & 63;
    int seg = threadIdx.x >> 6;
    int lo = half ? NU : 0, hi = half ? NT : NU;
    float s = 0.f;
    for (int r = lo + seg; r < hi; r += 4) s += g_V[(size_t)r * 64 + c];
    __shared__ float red[4][64];
    red[seg][c] = s;
    __syncthreads();
    if (seg == 0) g_csV[half * 64 + c] = red[0][c] + red[1][c] + red[2][c] + red[3][c];
}

// ---------------- k_mma: HMMA (mma.sync bf16) SYRK + GF panels ----------------
// SYRK tile pair (bi,bj): Su/Si = (Ahi+Alo)(gi) x M(gj)^T per half, scaled epilogue.
// GF block: GF = M(gi) x (Whi+Wlo)^T.
__global__ __launch_bounds__(256, 1) void k_mma() {
    extern __shared__ char smem[];
    uint32_t sb = smem_u32(smem);
    int tid = threadIdx.x;
    int wid = tid >> 5;
    int lane = tid & 31;

    int blk = blockIdx.x;
    int bi, bj;
    bool gfm;
    if (blk < 528) {
        int l = blk; bi = 0;
        while (l > bi) { l -= (bi + 1); bi++; }
        bj = l; gfm = false;
    } else {
        bi = blk - 528; bj = 0; gfm = true;
    }
    int gi0 = bi * 128, gj0 = bj * 128;

    // ---- loader setup: 6 x 16B per thread per stage ----
    uint32_t dstoff[6];
    const char* srcp[6];
    #pragma unroll
    for (int i = 0; i < 6; i++) {
        int flat = tid + i * 256;
        int mat = flat >> 9;            // 0..2
        int row = (flat >> 2) & 127;
        int ch  = flat & 3;
        const __nv_bfloat16* bas;
        if (!gfm) {
            bas = (mat == 0) ? g_Ahi + (size_t)(gi0 + row) * KP
                : (mat == 1) ? g_Alo + (size_t)(gi0 + row) * KP
                             : g_M   + (size_t)(gj0 + row) * KP;
        } else {
            bas = (mat == 0) ? g_M   + (size_t)(gi0 + row) * KP
                : (mat == 1) ? g_Whi + (size_t)row * KP
                             : g_Wlo + (size_t)row * KP;
        }
        srcp[i] = (const char*)(bas + ch * 8);
        dstoff[i] = (uint32_t)(mat * MAT_SZ + row * 64 + ((ch ^ ((row >> 1) & 3)) << 4));
    }

    // ---- accumulators ----
    float accU[2][8][4], accI[2][8][4];
    #pragma unroll
    for (int a = 0; a < 2; a++)
        #pragma unroll
        for (int b = 0; b < 8; b++)
            #pragma unroll
            for (int c = 0; c < 4; c++) { accU[a][b][c] = 0.f; accI[a][b][c] = 0.f; }

    int wm = wid & 3, wn = wid >> 2;
    int mr0 = wm * 32, nr0 = wn * 64;

    // prologue: stages 0,1
    #pragma unroll
    for (int i = 0; i < 6; i++) cpasync16(sb + dstoff[i], srcp[i]);
    CP_COMMIT();
    #pragma unroll
    for (int i = 0; i < 6; i++) cpasync16(sb + STG + dstoff[i], srcp[i] + KC * 2);
    CP_COMMIT();

    for (int step = 0; step < NSTEP; step++) {
        CP_WAIT1();
        __syncthreads();
        if (step + 2 < NSTEP) {
            uint32_t dstage = sb + (uint32_t)((step + 2) % 3) * STG;
            size_t soff = (size_t)(step + 2) * (KC * 2);
            #pragma unroll
            for (int i = 0; i < 6; i++) cpasync16(dstage + dstoff[i], srcp[i] + soff);
        }
        CP_COMMIT();

        uint32_t mb = sb + (uint32_t)(step % 3) * STG;
        uint32_t m0b = mb, m1b = mb + MAT_SZ, m2b = mb + 2 * MAT_SZ;

        #define LDA(FR, MB, MR, KI) { \
            int _r = (MR) + (lane & 15); \
            int _c = 2 * (KI) + (lane >> 4); \
            ldsm4(FR[0], FR[1], FR[2], FR[3], (MB) + _r * 64 + (((_c) ^ ((_r >> 1) & 3)) << 4)); }
        #define LDB(FR, MB, NR, KI) { \
            int _r = (NR) + (lane & 7) + ((lane >> 4) & 1) * 8; \
            int _c = 2 * (KI) + ((lane >> 3) & 1); \
            ldsm4(FR[0], FR[1], FR[2], FR[3], (MB) + _r * 64 + (((_c) ^ ((_r >> 1) & 3)) << 4)); }

        #define SYRK_K16(ACC, KI) { \
            uint32_t aH[2][4], aL[2][4], bb[4][4]; \
            LDA(aH[0], m0b, mr0, KI); LDA(aH[1], m0b, mr0 + 16, KI); \
            LDA(aL[0], m1b, mr0, KI); LDA(aL[1], m1b, mr0 + 16, KI); \
            LDB(bb[0], m2b, nr0, KI); LDB(bb[1], m2b, nr0 + 16, KI); \
            LDB(bb[2], m2b, nr0 + 32, KI); LDB(bb[3], m2b, nr0 + 48, KI); \
            _Pragma("unroll") \
            for (int mi = 0; mi < 2; mi++) \
                _Pragma("unroll") \
                for (int t = 0; t < 4; t++) \
                    _Pragma("unroll") \
                    for (int s2 = 0; s2 < 2; s2++) { \
                        mma16816(ACC[mi][t * 2 + s2], aH[mi], &bb[t][2 * s2]); \
                        mma16816(ACC[mi][t * 2 + s2], aL[mi], &bb[t][2 * s2]); \
                    } }

        #define GF_K16(ACC, KI) { \
            uint32_t af[2][4], bh[4][4], bl[4][4]; \
            LDA(af[0], m0b, mr0, KI); LDA(af[1], m0b, mr0 + 16, KI); \
            LDB(bh[0], m1b, nr0, KI); LDB(bh[1], m1b, nr0 + 16, KI); \
            LDB(bh[2], m1b, nr0 + 32, KI); LDB(bh[3], m1b, nr0 + 48, KI); \
            LDB(bl[0], m2b, nr0, KI); LDB(bl[1], m2b, nr0 + 16, KI); \
            LDB(bl[2], m2b, nr0 + 32, KI); LDB(bl[3], m2b, nr0 + 48, KI); \
            _Pragma("unroll") \
            for (int mi = 0; mi < 2; mi++) \
                _Pragma("unroll") \
                for (int t = 0; t < 4; t++) \
                    _Pragma("unroll") \
                    for (int s2 = 0; s2 < 2; s2++) { \
                        mma16816(ACC[mi][t * 2 + s2], af[mi], &bh[t][2 * s2]); \
                        mma16816(ACC[mi][t * 2 + s2], af[mi], &bl[t][2 * s2]); \
                    } }

        if (!gfm) {
            if (step < STEP_U) { SYRK_K16(accU, 0); SYRK_K16(accU, 1); }
            else               { SYRK_K16(accI, 0); SYRK_K16(accI, 1); }
        } else {
            GF_K16(accI, 0); GF_K16(accI, 1);
        }
    }
    __syncthreads();

    // ---- epilogue ----
    float* szu  = (float*)(smem + 0);
    float* szi  = (float*)(smem + 512);
    int*   sfl  = (int*)  (smem + 1024);
    float* scsv = (float*)(smem + 1536);
    if (tid < 128) {
        if (!gfm) {
            int h = gj0 + tid;
            szu[tid] = g_iZ[h];
            szi[tid] = g_iZ[G + h];
            sfl[tid] = (g_degf[h] ? 1 : 0) | (g_degf[G + h] ? 2 : 0);
        } else {
            scsv[tid] = g_csV[tid];
        }
    }
    __syncthreads();

    int gid = lane >> 2, qc = (lane & 3) * 2;
    if (!gfm) {
        #pragma unroll
        for (int mi = 0; mi < 2; mi++) {
            #pragma unroll
            for (int rh = 0; rh < 2; rh++) {
                int r = gi0 + mr0 + mi * 16 + gid + rh * 8;
                float gzu = g_iZ[r], gzi = g_iZ[G + r];
                int gfl = (g_degf[r] ? 1 : 0) | (g_degf[G + r] ? 2 : 0);
                #pragma unroll
                for (int nj = 0; nj < 8; nj++) {
                    #pragma unroll
                    for (int e = 0; e < 2; e++) {
                        int cl = nr0 + nj * 8 + qc + e;
                        int fl = sfl[cl] | gfl;
                        float su = accU[mi][nj][rh * 2 + e];
                        float si = accI[mi][nj][rh * 2 + e];
                        float tu = (fl & 1) ? INV_NU : su * gzu * szu[cl];
                        float ti = (fl & 2) ? INV_NI : si * gzi * szi[cl];
                        float v = tu + ti;
                        g_wp[(size_t)r * G + gj0 + cl] = v;
                        if (bi != bj) g_wp[(size_t)(gj0 + cl) * G + r] = v;
                    }
                }
            }
        }
    } else {
        #pragma unroll
        for (int mi = 0; mi < 2; mi++) {
            #pragma unroll
            for (int rh = 0; rh < 2; rh++) {
                int r = gi0 + mr0 + mi * 16 + gid + rh * 8;
                float gzu = g_iZ[r], gzi = g_iZ[G + r];
                int gfl = (g_degf[r] ? 1 : 0) | (g_degf[G + r] ? 2 : 0);
                #pragma unroll
                for (int nj = 0; nj < 8; nj++) {
                    #pragma unroll
                    for (int e = 0; e < 2; e++) {
                        int cl = nr0 + nj * 8 + qc + e;
                        float a = accI[mi][nj][rh * 2 + e];
                        float v = (cl < 64)
                            ? ((gfl & 1) ? INV_NU * scsv[cl] : a * gzu)
                            : ((gfl & 2) ? INV_NI * scsv[cl] : a * gzi);
                        g_GF[(size_t)r * 128 + cl] = v;
                    }
                }
            }
        }
    }
}

// ---------------- k_norm ----------------
__global__ void k_norm() {
    int g = blockIdx.x * 256 + threadIdx.x;
    if (g < G) g_norm[g] = sqrtf(g_wp[(size_t)g * G + g]);
}

// ---------------- k_msg ----------------
__global__ void k_msg() {
    int h0 = blockIdx.x * 32;
    int tx = threadIdx.x & 15, ty = threadIdx.x >> 4;
    __shared__ float wpS[32][17];
    __shared__ float gfS[16][128];
    __shared__ float nS[16];
    float nh0 = g_norm[h0 + ty * 2];
    float nh1 = g_norm[h0 + ty * 2 + 1];
    float macc[2][8];
    #pragma unroll
    for (int i = 0; i < 2; i++)
        #pragma unroll
        for (int j = 0; j < 8; j++) macc[i][j] = 0.f;
    float dacc[2] = {0.f, 0.f};
    int lrow = threadIdx.x >> 5, lc4 = (threadIdx.x & 31) * 4;
    int wrow = threadIdx.x >> 3, wcol = (threadIdx.x & 7) * 2;

    for (int k0 = 0; k0 < G; k0 += 16) {
        float2 wv = *(const float2*)&g_wp[(size_t)(h0 + wrow) * G + k0 + wcol];
        wpS[wrow][wcol] = wv.x;
        wpS[wrow][wcol + 1] = wv.y;
        *(float4*)&gfS[lrow][lc4]     = *(const float4*)&g_GF[(size_t)(k0 + lrow) * 128 + lc4];
        *(float4*)&gfS[lrow + 8][lc4] = *(const float4*)&g_GF[(size_t)(k0 + lrow + 8) * 128 + lc4];
        if (threadIdx.x < 16) nS[threadIdx.x] = g_norm[k0 + threadIdx.x];
        __syncthreads();
        #pragma unroll
        for (int kk = 0; kk < 16; kk++) {
            float ng = nS[kk];
            float a0 = __fdividef(wpS[ty * 2][kk],     nh0 * ng + EPSL);
            float a1 = __fdividef(wpS[ty * 2 + 1][kk], nh1 * ng + EPSL);
            dacc[0] += a0; dacc[1] += a1;
            #pragma unroll
            for (int j = 0; j < 8; j++) {
                float b = gfS[kk][tx * 8 + j];
                macc[0][j] += a0 * b;
                macc[1][j] += a1 * b;
            }
        }
        __syncthreads();
    }
    #pragma unroll
    for (int ii = 0; ii < 2; ii++) {
        int h = h0 + ty * 2 + ii;
        #pragma unroll
        for (int j = 0; j < 8; j++) g_msg[h * 128 + tx * 8 + j] = macc[ii][j];
        if (tx == 0) g_deg[h] = dacc[ii];
    }
}

// ---------------- k_out ----------------
__global__ void k_out(const float* __restrict__ gW, const float* __restrict__ gb,
                      float* __restrict__ out) {
    int g = blockIdx.x;
    int t = threadIdx.x;
    __shared__ float aggS[128];
    float dg = g_deg[g];
    float invd = (dg > 0.f) ? 1.f / dg : 0.f;
    for (int c = t; c < 128; c += 64) {
        float hn = g_msg[g * 128 + c] * invd;
        aggS[c] = ALPHA * g_GF[g * 128 + c] + (1.f - ALPHA) * hn;
    }
    __syncthreads();
    float acc = gb[t];
    #pragma unroll
    for (int c = 0; c < 128; c++) acc += aggS[c] * gW[t * 128 + c];
    out[g * 64 + t] = 1.f / (1.f + expf(-acc));
}

// ---------------- launch ----------------
extern "C" void kernel_launch(void* const* d_in, const int* in_sizes, int n_in,
                              void* d_out, int out_size) {
    int base = (in_sizes[2] == 1) ? 3 : 2;
    const int*   H   = (const int*)d_in[0];
    const float* X   = (const float*)d_in[1];
    const float* uWq = (const float*)d_in[base + 0];
    const float* ubq = (const float*)d_in[base + 1];
    const float* uWk = (const float*)d_in[base + 2];
    const float* ubk = (const float*)d_in[base + 3];
    const float* uWv = (const float*)d_in[base + 4];
    const float* ubv = (const float*)d_in[base + 5];
    const float* uWs = (const float*)d_in[base + 6];
    const float* ubs = (const float*)d_in[base + 7];
    const float* iWq = (const float*)d_in[base + 8];
    const float* ibq = (const float*)d_in[base + 9];
    const float* iWk = (const float*)d_in[base + 10];
    const float* ibk = (const float*)d_in[base + 11];
    const float* iWv = (const float*)d_in[base + 12];
    const float* ibv = (const float*)d_in[base + 13];
    const float* iWs = (const float*)d_in[base + 14];
    const float* ibs = (const float*)d_in[base + 15];
    const float* gW  = (const float*)d_in[base + 16];
    const float* gb  = (const float*)d_in[base + 17];
    float* out = (float*)d_out;

    static int smem_set = 0;
    if (!smem_set) {
        cudaFuncSetAttribute(k_mma, cudaFuncAttributeMaxDynamicSharedMemorySize, SMEM_MMA);
        smem_set = 1;
    }

    k_zero<<<32, 256>>>();
    k_reduce<<<dim3(20, 2), 256>>>(X, uWs, iWs);
    k_prep<<<1, 64>>>(uWk, ubk, uWq, ubq, ubs, iWk, ibk, iWq, ibq, ibs);
    k_ev<<<563, 256>>>(X, uWv, ubv, iWv, ibv);
    k_z<<<dim3(16, 18), 256>>>(H);
    k_inv<<<32, 256>>>();
    k_pack<<<dim3(32, 283), 256>>>(H);
    k_w<<<283, 256>>>();
    k_csv<<<2, 256>>>();
    k_mma<<<560, 256, SMEM_MMA>>>();
    k_norm<<<16, 256>>>();
    k_msg<<<128, 256>>>();
    k_out<<<G, 64>>>(gW, gb, out);
}

// round 13
// speedup vs baseline: 3.3421x; 1.1160x over previous
#include <cuda_runtime.h>
#include <cuda_bf16.h>
#include <cstdint>

// ---------------- problem constants ----------------
#define NU 8000
#define NI 10000
#define NT 18000
#define G  4096
#define KPU 8064          // u-half padded rows (126*64)
#define KP  18112         // total padded K
#define ALPHA 0.8f
#define EPSL  1e-8f
#define INV_NU (1.0f/8000.0f)
#define INV_NI (1.0f/10000.0f)

// k_mma tiling
#define KC 32
#define NSTEP 566         // KP/KC
#define STEP_U 252        // KPU/KC
#define MAT_SZ 8192       // 128 rows * 64 B
#define STG    24576      // 3 mats
#define SMEM_MMA 73728    // 3 stages

// ---------------- device scratch ----------------
__device__ __align__(256) __nv_bfloat16 g_Ahi[(size_t)G * KP]; // m*E^2 hi
__device__ __align__(256) __nv_bfloat16 g_Alo[(size_t)G * KP]; // m*E^2 lo
__device__ __align__(256) __nv_bfloat16 g_M  [(size_t)G * KP]; // binary mask
__device__ __align__(256) __nv_bfloat16 g_Whi[(size_t)128 * KP]; // E*V hi (transposed, zero-padded per half)
__device__ __align__(256) __nv_bfloat16 g_Wlo[(size_t)128 * KP];
__device__ __align__(256) float g_V[(size_t)NT * 64];
__device__ float g_E[NT];
__device__ float g_Z[2 * G];
__device__ int   g_cnt[2 * G];
__device__ float g_iZ[2 * G];
__device__ int   g_degf[2 * G];
__device__ float g_csV[128];
__device__ __align__(256) float g_wp[(size_t)G * G];
__device__ __align__(256) float g_GF[G * 128];
__device__ float g_msg[G * 128];
__device__ float g_deg[G];
__device__ float g_norm[G];
__device__ float g_red[2 * 65];
__device__ float g_uvec[2 * 64];
__device__ float g_ccon[2];

// ---------------- PTX helpers (base compute_103 — no 'a'-features) ----------------
__device__ __forceinline__ uint32_t smem_u32(const void* p) {
    uint32_t a;
    asm("{ .reg .u64 t; cvta.to.shared.u64 t, %1; cvt.u32.u64 %0, t; }" : "=r"(a) : "l"(p));
    return a;
}
__device__ __forceinline__ void cpasync16(uint32_t dst, const void* src) {
    asm volatile("cp.async.cg.shared.global [%0], [%1], 16;" :: "r"(dst), "l"(src) : "memory");
}
#define CP_COMMIT() asm volatile("cp.async.commit_group;" ::: "memory")
#define CP_WAIT1()  asm volatile("cp.async.wait_group 1;" ::: "memory")

__device__ __forceinline__ void ldsm4(uint32_t& r0, uint32_t& r1, uint32_t& r2, uint32_t& r3,
                                      uint32_t addr) {
    asm volatile("ldmatrix.sync.aligned.m8n8.x4.shared.b16 {%0,%1,%2,%3}, [%4];"
                 : "=r"(r0), "=r"(r1), "=r"(r2), "=r"(r3) : "r"(addr));
}
__device__ __forceinline__ void mma16816(float* c, const uint32_t* a, const uint32_t* b) {
    asm volatile(
        "mma.sync.aligned.m16n8k16.row.col.f32.bf16.bf16.f32 "
        "{%0,%1,%2,%3}, {%4,%5,%6,%7}, {%8,%9}, {%0,%1,%2,%3};"
        : "+f"(c[0]), "+f"(c[1]), "+f"(c[2]), "+f"(c[3])
        : "r"(a[0]), "r"(a[1]), "r"(a[2]), "r"(a[3]), "r"(b[0]), "r"(b[1]));
}

// ---------------- k_zero ----------------
__global__ void k_zero() {
    int i = blockIdx.x * blockDim.x + threadIdx.x;
    if (i < 2 * 65) g_red[i] = 0.f;
    if (i < 2 * G) { g_Z[i] = 0.f; g_cnt[i] = 0; }
}

// ---------------- k_reduce: r = sum_m Ws[m] x[m,:], sw = sum Ws ----------------
__global__ void k_reduce(const float* __restrict__ x,
                         const float* __restrict__ uWs,
                         const float* __restrict__ iWs) {
    int half = blockIdx.y;
    int m0 = blockIdx.x * 500;
    int Nh = half ? NI : NU;
    if (m0 >= Nh) return;
    const float* Ws = half ? iWs : uWs;
    int off = half ? NU : 0;
    int md = threadIdx.x >> 6;
    int dd = threadIdx.x & 63;
    float acc = 0.f, sw = 0.f;
    int m1 = min(m0 + 500, Nh);
    for (int m = m0 + md; m < m1; m += 4) {
        float w = Ws[m];
        acc += w * x[(size_t)(off + m) * 64 + dd];
        if (dd == 0) sw += w;
    }
    __shared__ float sA[4][64];
    __shared__ float sW[4];
    sA[md][dd] = acc;
    if (dd == 0) sW[md] = sw;
    __syncthreads();
    if (md == 0) {
        float t = sA[0][dd] + sA[1][dd] + sA[2][dd] + sA[3][dd];
        atomicAdd(&g_red[half * 65 + dd], t);
        if (dd == 0) atomicAdd(&g_red[half * 65 + 64], sW[0] + sW[1] + sW[2] + sW[3]);
    }
}

// ---------------- k_prep ----------------
__global__ void k_prep(const float* __restrict__ uWk, const float* __restrict__ ubk,
                       const float* __restrict__ uWq, const float* __restrict__ ubq,
                       const float* __restrict__ ubs,
                       const float* __restrict__ iWk, const float* __restrict__ ibk,
                       const float* __restrict__ iWq, const float* __restrict__ ibq,
                       const float* __restrict__ ibs) {
    __shared__ float rS[64], tS[64];
    int t = threadIdx.x;
    for (int half = 0; half < 2; half++) {
        const float* Wk = half ? iWk : uWk; const float* bk = half ? ibk : ubk;
        const float* Wq = half ? iWq : uWq; const float* bq = half ? ibq : ubq;
        const float* bs = half ? ibs : ubs;
        rS[t] = g_red[half * 65 + t];
        __syncthreads();
        float sw = g_red[half * 65 + 64];
        float tv = 0.f;
        for (int d = 0; d < 64; d++) tv += Wk[t * 64 + d] * rS[d];
        tv += sw * bk[t];
        tS[t] = tv;
        __syncthreads();
        float u = 0.f;
        for (int hd = 0; hd < 64; hd++) u += Wq[hd * 64 + t] * tS[hd];
        g_uvec[half * 64 + t] = u;
        if (t == 0) {
            float c = bs[0];
            for (int hd = 0; hd < 64; hd++) c += bq[hd] * tS[hd];
            g_ccon[half] = c;
        }
        __syncthreads();
    }
}

// ---------------- k_ev: V rows + E=exp(s) (32 rows per block) ----------------
__global__ __launch_bounds__(256) void k_ev(const float* __restrict__ x,
                     const float* __restrict__ uWv, const float* __restrict__ ubv,
                     const float* __restrict__ iWv, const float* __restrict__ ibv) {
    int r0 = blockIdx.x * 32;
    int half = (r0 >= NU) ? 1 : 0;
    const float* Wv = half ? iWv : uWv;
    const float* bv = half ? ibv : ubv;
    __shared__ float wS[64][65];
    __shared__ float xS[32][65];
    __shared__ float bS[64], uS[64];
    int tid = threadIdx.x;
    for (int i = tid; i < 4096; i += 256) wS[i >> 6][i & 63] = Wv[i];
    if (tid < 64) { bS[tid] = bv[tid]; uS[tid] = g_uvec[half * 64 + tid]; }
    for (int i = tid; i < 2048; i += 256) {
        int rr = i >> 6;
        int gr = r0 + rr;
        xS[rr][i & 63] = (gr < NT) ? x[(size_t)gr * 64 + (i & 63)] : 0.f;
    }
    __syncthreads();
    int row = tid >> 3;
    int c0 = (tid & 7) * 8;
    float v[8];
    #pragma unroll
    for (int j = 0; j < 8; j++) v[j] = bS[c0 + j];
    #pragma unroll 8
    for (int d = 0; d < 64; d++) {
        float xv = xS[row][d];
        #pragma unroll
        for (int j = 0; j < 8; j++) v[j] += wS[c0 + j][d] * xv;
    }
    int gr = r0 + row;
    if (gr < NT) {
        #pragma unroll
        for (int j = 0; j < 8; j++) g_V[(size_t)gr * 64 + c0 + j] = v[j];
    }
    float p = 0.f;
    #pragma unroll
    for (int j = 0; j < 8; j++) p += xS[row][c0 + j] * uS[c0 + j];
    p += __shfl_xor_sync(0xffffffff, p, 1);
    p += __shfl_xor_sync(0xffffffff, p, 2);
    p += __shfl_xor_sync(0xffffffff, p, 4);
    if ((tid & 7) == 0 && gr < NT) g_E[gr] = expf(p + g_ccon[half]);
}

// ---------------- k_z: Z_g and counts per half ----------------
__global__ void k_z(const int* __restrict__ H) {
    int gcol = blockIdx.x * 256 + threadIdx.x;
    int n0 = blockIdx.y * 1000;
    int half = (n0 >= NU) ? 1 : 0;
    __shared__ float eS[1000];
    for (int i = threadIdx.x; i < 1000; i += 256) eS[i] = g_E[n0 + i];
    __syncthreads();
    float z = 0.f; int c = 0;
    const int* Hp = H + (size_t)n0 * G + gcol;
    for (int i = 0; i < 1000; i++) {
        if (Hp[(size_t)i * G] != 0) { z += eS[i]; c++; }
    }
    atomicAdd(&g_Z[half * G + gcol], z);
    atomicAdd(&g_cnt[half * G + gcol], c);
}

// ---------------- k_inv ----------------
__global__ void k_inv() {
    int i = blockIdx.x * 256 + threadIdx.x;
    if (i < 2 * G) {
        int c = g_cnt[i];
        g_iZ[i] = (c > 0) ? 1.f / g_Z[i] : 0.f;
        g_degf[i] = (c == 0) ? 1 : 0;
    }
}

// ---------------- k_pack: Ahi/Alo = split(m*E^2), M = m (K-major panels) ----------------
__global__ __launch_bounds__(256) void k_pack(const int* __restrict__ H) {
    int g0 = blockIdx.x * 128;
    int n0 = blockIdx.y * 64;
    bool half_i = (n0 >= KPU);
    __shared__ float e2s[64];
    __shared__ int gns[64];
    int tid = threadIdx.x;
    if (tid < 64) {
        int n = n0 + tid;
        int gn;
        if (!half_i) gn = (n < NU) ? n : -1;
        else { int k = n - KPU; gn = (k < NI) ? (NU + k) : -1; }
        gns[tid] = gn;
        float e = (gn >= 0) ? g_E[gn] : 0.f;
        e2s[tid] = e * e;
    }
    __syncthreads();
    int gl = tid & 127;
    int g = g0 + gl;
    bool dead = (g_cnt[(half_i ? G : 0) + g] == 0);
    int cgrp = tid >> 7;
    union U8 { __nv_bfloat16 h[8]; uint4 v; };
    for (int q = 0; q < 4; q++) {
        int ck = cgrp * 4 + q;
        U8 uh, ul, um;
        #pragma unroll
        for (int j = 0; j < 8; j++) {
            int nl = ck * 8 + j;
            int gn = gns[nl];
            float a = 0.f;
            float mv = 0.f;
            if (gn >= 0 && !dead) {
                int h = H[(size_t)gn * G + g];
                if (h != 0) { a = e2s[nl]; mv = 1.f; }
            }
            __nv_bfloat16 ah = __float2bfloat16(a);
            uh.h[j] = ah;
            ul.h[j] = __float2bfloat16(a - __bfloat162float(ah));
            um.h[j] = __float2bfloat16(mv);
        }
        size_t off = (size_t)g * KP + n0 + ck * 8;
        *(uint4*)&g_Ahi[off] = uh.v;
        *(uint4*)&g_Alo[off] = ul.v;
        *(uint4*)&g_M[off]   = um.v;
    }
}

// ---------------- k_w: Whi/Wlo[c][n] = split(E[n]*R2[n][c]) ----------------
__global__ __launch_bounds__(256) void k_w() {
    int n0 = blockIdx.x * 64;
    bool half_i = (n0 >= KPU);
    __shared__ float es[64];
    __shared__ int gns[64];
    int tid = threadIdx.x;
    if (tid < 64) {
        int n = n0 + tid;
        int gn;
        if (!half_i) gn = (n < NU) ? n : -1;
        else { int k = n - KPU; gn = (k < NI) ? (NU + k) : -1; }
        gns[tid] = gn;
        es[tid] = (gn >= 0) ? g_E[gn] : 0.f;
    }
    __syncthreads();
    int c = tid & 127;
    int cgrp = tid >> 7;
    bool active = half_i ? (c >= 64) : (c < 64);
    int vc = half_i ? (c - 64) : c;
    union U8 { __nv_bfloat16 h[8]; uint4 v; };
    for (int q = 0; q < 4; q++) {
        int ck = cgrp * 4 + q;
        U8 uh, ul;
        #pragma unroll
        for (int j = 0; j < 8; j++) {
            int nl = ck * 8 + j;
            int gn = gns[nl];
            float w = 0.f;
            if (active && gn >= 0) w = es[nl] * g_V[(size_t)gn * 64 + vc];
            __nv_bfloat16 wh = __float2bfloat16(w);
            uh.h[j] = wh;
            ul.h[j] = __float2bfloat16(w - __bfloat162float(wh));
        }
        size_t off = (size_t)c * KP + n0 + ck * 8;
        *(uint4*)&g_Whi[off] = uh.v;
        *(uint4*)&g_Wlo[off] = ul.v;
    }
}

// ---------------- k_csv: column sums of V per half ----------------
__global__ void k_csv() {
    int half = blockIdx.x;
    int c = threadIdx.x & 63;
    int seg = threadIdx.x >> 6;
    int lo = half ? NU : 0, hi = half ? NT : NU;
    float s = 0.f;
    for (int r = lo + seg; r < hi; r += 4) s += g_V[(size_t)r * 64 + c];
    __shared__ float red[4][64];
    red[seg][c] = s;
    __syncthreads();
    if (seg == 0) g_csV[half * 64 + c] = red[0][c] + red[1][c] + red[2][c] + red[3][c];
}

// ---------------- k_mma: HMMA SYRK + GF panels, single accumulator, 2 CTA/SM ----------------
// SYRK tile (bi,bj): u-phase accumulates, flushes scaled tu to g_wp mid-loop (no sync
// needed: regs+gmem only), i-phase accumulates, final epilogue adds ti and writes sym.
__global__ __launch_bounds__(256, 2) void k_mma() {
    extern __shared__ char smem[];
    uint32_t sb = smem_u32(smem);
    int tid = threadIdx.x;
    int wid = tid >> 5;
    int lane = tid & 31;

    int blk = blockIdx.x;
    int bi, bj;
    bool gfm;
    if (blk < 528) {
        int l = blk; bi = 0;
        while (l > bi) { l -= (bi + 1); bi++; }
        bj = l; gfm = false;
    } else {
        bi = blk - 528; bj = 0; gfm = true;
    }
    int gi0 = bi * 128, gj0 = bj * 128;

    // ---- loader setup: 6 x 16B per thread per stage ----
    uint32_t dstoff[6];
    const char* srcp[6];
    #pragma unroll
    for (int i = 0; i < 6; i++) {
        int flat = tid + i * 256;
        int mat = flat >> 9;            // 0..2
        int row = (flat >> 2) & 127;
        int ch  = flat & 3;
        const __nv_bfloat16* bas;
        if (!gfm) {
            bas = (mat == 0) ? g_Ahi + (size_t)(gi0 + row) * KP
                : (mat == 1) ? g_Alo + (size_t)(gi0 + row) * KP
                             : g_M   + (size_t)(gj0 + row) * KP;
        } else {
            bas = (mat == 0) ? g_M   + (size_t)(gi0 + row) * KP
                : (mat == 1) ? g_Whi + (size_t)row * KP
                             : g_Wlo + (size_t)row * KP;
        }
        srcp[i] = (const char*)(bas + ch * 8);
        dstoff[i] = (uint32_t)(mat * MAT_SZ + row * 64 + ((ch ^ ((row >> 1) & 3)) << 4));
    }

    // ---- single accumulator set ----
    float acc[2][8][4];
    #pragma unroll
    for (int a = 0; a < 2; a++)
        #pragma unroll
        for (int b = 0; b < 8; b++)
            #pragma unroll
            for (int c = 0; c < 4; c++) acc[a][b][c] = 0.f;

    int wm = wid & 3, wn = wid >> 2;
    int mr0 = wm * 32, nr0 = wn * 64;
    int gid = lane >> 2, qc = (lane & 3) * 2;

    // prologue: stages 0,1
    #pragma unroll
    for (int i = 0; i < 6; i++) cpasync16(sb + dstoff[i], srcp[i]);
    CP_COMMIT();
    #pragma unroll
    for (int i = 0; i < 6; i++) cpasync16(sb + STG + dstoff[i], srcp[i] + KC * 2);
    CP_COMMIT();

    for (int step = 0; step < NSTEP; step++) {
        CP_WAIT1();
        __syncthreads();
        if (step + 2 < NSTEP) {
            uint32_t dstage = sb + (uint32_t)((step + 2) % 3) * STG;
            size_t soff = (size_t)(step + 2) * (KC * 2);
            #pragma unroll
            for (int i = 0; i < 6; i++) cpasync16(dstage + dstoff[i], srcp[i] + soff);
        }
        CP_COMMIT();

        uint32_t mb = sb + (uint32_t)(step % 3) * STG;
        uint32_t m0b = mb, m1b = mb + MAT_SZ, m2b = mb + 2 * MAT_SZ;

        #define LDA(FR, MB, MR, KI) { \
            int _r = (MR) + (lane & 15); \
            int _c = 2 * (KI) + (lane >> 4); \
            ldsm4(FR[0], FR[1], FR[2], FR[3], (MB) + _r * 64 + (((_c) ^ ((_r >> 1) & 3)) << 4)); }
        #define LDB(FR, MB, NR, KI) { \
            int _r = (NR) + (lane & 7) + ((lane >> 4) & 1) * 8; \
            int _c = 2 * (KI) + ((lane >> 3) & 1); \
            ldsm4(FR[0], FR[1], FR[2], FR[3], (MB) + _r * 64 + (((_c) ^ ((_r >> 1) & 3)) << 4)); }

        #define SYRK_K16(ACC, KI) { \
            uint32_t aH[2][4], aL[2][4], bb[4][4]; \
            LDA(aH[0], m0b, mr0, KI); LDA(aH[1], m0b, mr0 + 16, KI); \
            LDA(aL[0], m1b, mr0, KI); LDA(aL[1], m1b, mr0 + 16, KI); \
            LDB(bb[0], m2b, nr0, KI); LDB(bb[1], m2b, nr0 + 16, KI); \
            LDB(bb[2], m2b, nr0 + 32, KI); LDB(bb[3], m2b, nr0 + 48, KI); \
            _Pragma("unroll") \
            for (int mi = 0; mi < 2; mi++) \
                _Pragma("unroll") \
                for (int t = 0; t < 4; t++) \
                    _Pragma("unroll") \
                    for (int s2 = 0; s2 < 2; s2++) { \
                        mma16816(ACC[mi][t * 2 + s2], aH[mi], &bb[t][2 * s2]); \
                        mma16816(ACC[mi][t * 2 + s2], aL[mi], &bb[t][2 * s2]); \
                    } }

        #define GF_K16(ACC, KI) { \
            uint32_t af[2][4], bh[4][4], bl[4][4]; \
            LDA(af[0], m0b, mr0, KI); LDA(af[1], m0b, mr0 + 16, KI); \
            LDB(bh[0], m1b, nr0, KI); LDB(bh[1], m1b, nr0 + 16, KI); \
            LDB(bh[2], m1b, nr0 + 32, KI); LDB(bh[3], m1b, nr0 + 48, KI); \
            LDB(bl[0], m2b, nr0, KI); LDB(bl[1], m2b, nr0 + 16, KI); \
            LDB(bl[2], m2b, nr0 + 32, KI); LDB(bl[3], m2b, nr0 + 48, KI); \
            _Pragma("unroll") \
            for (int mi = 0; mi < 2; mi++) \
                _Pragma("unroll") \
                for (int t = 0; t < 4; t++) \
                    _Pragma("unroll") \
                    for (int s2 = 0; s2 < 2; s2++) { \
                        mma16816(ACC[mi][t * 2 + s2], af[mi], &bh[t][2 * s2]); \
                        mma16816(ACC[mi][t * 2 + s2], af[mi], &bl[t][2 * s2]); \
                    } }

        if (!gfm) {
            SYRK_K16(acc, 0); SYRK_K16(acc, 1);
            if (step == STEP_U - 1) {
                // ---- mid-loop flush of scaled u-partial (regs + gmem only) ----
                #pragma unroll
                for (int mi = 0; mi < 2; mi++) {
                    #pragma unroll
                    for (int rh = 0; rh < 2; rh++) {
                        int r = gi0 + mr0 + mi * 16 + gid + rh * 8;
                        float gzu = g_iZ[r];
                        int gfu = g_degf[r];
                        #pragma unroll
                        for (int nj = 0; nj < 8; nj++) {
                            #pragma unroll
                            for (int e = 0; e < 2; e++) {
                                int h = gj0 + nr0 + nj * 8 + qc + e;
                                float su = acc[mi][nj][rh * 2 + e];
                                float tu = (gfu | g_degf[h]) ? INV_NU : su * gzu * g_iZ[h];
                                g_wp[(size_t)r * G + h] = tu;
                                acc[mi][nj][rh * 2 + e] = 0.f;
                            }
                        }
                    }
                }
            }
        } else {
            GF_K16(acc, 0); GF_K16(acc, 1);
        }
    }
    __syncthreads();

    // ---- epilogue ----
    float* szi  = (float*)(smem + 0);
    int*   sfl  = (int*)  (smem + 512);
    float* scsv = (float*)(smem + 1024);
    if (tid < 128) {
        if (!gfm) {
            int h = gj0 + tid;
            szi[tid] = g_iZ[G + h];
            sfl[tid] = g_degf[G + h] ? 1 : 0;
        } else {
            scsv[tid] = g_csV[tid];
        }
    }
    __syncthreads();

    if (!gfm) {
        #pragma unroll
        for (int mi = 0; mi < 2; mi++) {
            #pragma unroll
            for (int rh = 0; rh < 2; rh++) {
                int r = gi0 + mr0 + mi * 16 + gid + rh * 8;
                float gzi = g_iZ[G + r];
                int gfi = g_degf[G + r];
                #pragma unroll
                for (int nj = 0; nj < 8; nj++) {
                    #pragma unroll
                    for (int e = 0; e < 2; e++) {
                        int cl = nr0 + nj * 8 + qc + e;
                        float si = acc[mi][nj][rh * 2 + e];
                        float ti = (gfi | sfl[cl]) ? INV_NI : si * gzi * szi[cl];
                        float v = g_wp[(size_t)r * G + gj0 + cl] + ti;
                        g_wp[(size_t)r * G + gj0 + cl] = v;
                        if (bi != bj) g_wp[(size_t)(gj0 + cl) * G + r] = v;
                    }
                }
            }
        }
    } else {
        #pragma unroll
        for (int mi = 0; mi < 2; mi++) {
            #pragma unroll
            for (int rh = 0; rh < 2; rh++) {
                int r = gi0 + mr0 + mi * 16 + gid + rh * 8;
                float gzu = g_iZ[r], gzi = g_iZ[G + r];
                int gfl = (g_degf[r] ? 1 : 0) | (g_degf[G + r] ? 2 : 0);
                #pragma unroll
                for (int nj = 0; nj < 8; nj++) {
                    #pragma unroll
                    for (int e = 0; e < 2; e++) {
                        int cl = nr0 + nj * 8 + qc + e;
                        float a = acc[mi][nj][rh * 2 + e];
                        float v = (cl < 64)
                            ? ((gfl & 1) ? INV_NU * scsv[cl] : a * gzu)
                            : ((gfl & 2) ? INV_NI * scsv[cl] : a * gzi);
                        g_GF[(size_t)r * 128 + cl] = v;
                    }
                }
            }
        }
    }
}

// ---------------- k_norm ----------------
__global__ void k_norm() {
    int g = blockIdx.x * 256 + threadIdx.x;
    if (g < G) g_norm[g] = sqrtf(g_wp[(size_t)g * G + g]);
}

// ---------------- k_msg ----------------
__global__ void k_msg() {
    int h0 = blockIdx.x * 32;
    int tx = threadIdx.x & 15, ty = threadIdx.x >> 4;
    __shared__ float wpS[32][17];
    __shared__ float gfS[16][128];
    __shared__ float nS[16];
    float nh0 = g_norm[h0 + ty * 2];
    float nh1 = g_norm[h0 + ty * 2 + 1];
    float macc[2][8];
    #pragma unroll
    for (int i = 0; i < 2; i++)
        #pragma unroll
        for (int j = 0; j < 8; j++) macc[i][j] = 0.f;
    float dacc[2] = {0.f, 0.f};
    int lrow = threadIdx.x >> 5, lc4 = (threadIdx.x & 31) * 4;
    int wrow = threadIdx.x >> 3, wcol = (threadIdx.x & 7) * 2;

    for (int k0 = 0; k0 < G; k0 += 16) {
        float2 wv = *(const float2*)&g_wp[(size_t)(h0 + wrow) * G + k0 + wcol];
        wpS[wrow][wcol] = wv.x;
        wpS[wrow][wcol + 1] = wv.y;
        *(float4*)&gfS[lrow][lc4]     = *(const float4*)&g_GF[(size_t)(k0 + lrow) * 128 + lc4];
        *(float4*)&gfS[lrow + 8][lc4] = *(const float4*)&g_GF[(size_t)(k0 + lrow + 8) * 128 + lc4];
        if (threadIdx.x < 16) nS[threadIdx.x] = g_norm[k0 + threadIdx.x];
        __syncthreads();
        #pragma unroll
        for (int kk = 0; kk < 16; kk++) {
            float ng = nS[kk];
            float a0 = __fdividef(wpS[ty * 2][kk],     nh0 * ng + EPSL);
            float a1 = __fdividef(wpS[ty * 2 + 1][kk], nh1 * ng + EPSL);
            dacc[0] += a0; dacc[1] += a1;
            #pragma unroll
            for (int j = 0; j < 8; j++) {
                float b = gfS[kk][tx * 8 + j];
                macc[0][j] += a0 * b;
                macc[1][j] += a1 * b;
            }
        }
        __syncthreads();
    }
    #pragma unroll
    for (int ii = 0; ii < 2; ii++) {
        int h = h0 + ty * 2 + ii;
        #pragma unroll
        for (int j = 0; j < 8; j++) g_msg[h * 128 + tx * 8 + j] = macc[ii][j];
        if (tx == 0) g_deg[h] = dacc[ii];
    }
}

// ---------------- k_out ----------------
__global__ void k_out(const float* __restrict__ gW, const float* __restrict__ gb,
                      float* __restrict__ out) {
    int g = blockIdx.x;
    int t = threadIdx.x;
    __shared__ float aggS[128];
    float dg = g_deg[g];
    float invd = (dg > 0.f) ? 1.f / dg : 0.f;
    for (int c = t; c < 128; c += 64) {
        float hn = g_msg[g * 128 + c] * invd;
        aggS[c] = ALPHA * g_GF[g * 128 + c] + (1.f - ALPHA) * hn;
    }
    __syncthreads();
    float acc = gb[t];
    #pragma unroll
    for (int c = 0; c < 128; c++) acc += aggS[c] * gW[t * 128 + c];
    out[g * 64 + t] = 1.f / (1.f + expf(-acc));
}

// ---------------- launch ----------------
extern "C" void kernel_launch(void* const* d_in, const int* in_sizes, int n_in,
                              void* d_out, int out_size) {
    int base = (in_sizes[2] == 1) ? 3 : 2;
    const int*   H   = (const int*)d_in[0];
    const float* X   = (const float*)d_in[1];
    const float* uWq = (const float*)d_in[base + 0];
    const float* ubq = (const float*)d_in[base + 1];
    const float* uWk = (const float*)d_in[base + 2];
    const float* ubk = (const float*)d_in[base + 3];
    const float* uWv = (const float*)d_in[base + 4];
    const float* ubv = (const float*)d_in[base + 5];
    const float* uWs = (const float*)d_in[base + 6];
    const float* ubs = (const float*)d_in[base + 7];
    const float* iWq = (const float*)d_in[base + 8];
    const float* ibq = (const float*)d_in[base + 9];
    const float* iWk = (const float*)d_in[base + 10];
    const float* ibk = (const float*)d_in[base + 11];
    const float* iWv = (const float*)d_in[base + 12];
    const float* ibv = (const float*)d_in[base + 13];
    const float* iWs = (const float*)d_in[base + 14];
    const float* ibs = (const float*)d_in[base + 15];
    const float* gW  = (const float*)d_in[base + 16];
    const float* gb  = (const float*)d_in[base + 17];
    float* out = (float*)d_out;

    static int smem_set = 0;
    if (!smem_set) {
        cudaFuncSetAttribute(k_mma, cudaFuncAttributeMaxDynamicSharedMemorySize, SMEM_MMA);
        smem_set = 1;
    }

    k_zero<<<32, 256>>>();
    k_reduce<<<dim3(20, 2), 256>>>(X, uWs, iWs);
    k_prep<<<1, 64>>>(uWk, ubk, uWq, ubq, ubs, iWk, ibk, iWq, ibq, ibs);
    k_ev<<<563, 256>>>(X, uWv, ubv, iWv, ibv);
    k_z<<<dim3(16, 18), 256>>>(H);
    k_inv<<<32, 256>>>();
    k_pack<<<dim3(32, 283), 256>>>(H);
    k_w<<<283, 256>>>();
    k_csv<<<2, 256>>>();
    k_mma<<<560, 256, SMEM_MMA>>>();
    k_norm<<<16, 256>>>();
    k_msg<<<128, 256>>>();
    k_out<<<G, 64>>>(gW, gb, out);
}

// round 14
// speedup vs baseline: 4.7307x; 1.4155x over previous
#include <cuda_runtime.h>
#include <cuda_bf16.h>
#include <cstdint>

// ---------------- problem constants ----------------
#define NU 8000
#define NI 10000
#define NT 18000
#define G  4096
#define KPU 8064          // u-half padded rows (126*64)
#define KP  18112         // total padded K
#define ALPHA 0.8f
#define EPSL  1e-8f
#define INV_NU (1.0f/8000.0f)
#define INV_NI (1.0f/10000.0f)

// k_mma tiling
#define KC 32
#define NSTEP 566         // KP/KC
#define STEP_U 252        // KPU/KC
#define MAT_SZ 8192       // 128 rows * 64 B
#define STG    16384      // 2 mats
#define SMEM_MMA 49152    // 3 stages

// ---------------- device scratch ----------------
__device__ __align__(256) __nv_bfloat16 g_A [(size_t)G * KP];   // bf16(m*E^2)
__device__ __align__(256) __nv_bfloat16 g_M [(size_t)G * KP];   // binary mask
__device__ __align__(256) __nv_bfloat16 g_W [(size_t)128 * KP]; // bf16(E*V) transposed, zero-padded per half
__device__ __align__(256) float g_V[(size_t)NT * 64];
__device__ float g_E[NT];
__device__ float g_Z[2 * G];
__device__ int   g_cnt[2 * G];
__device__ float g_iZ[2 * G];
__device__ int   g_degf[2 * G];
__device__ float g_csV[128];
__device__ __align__(256) float g_wp[(size_t)G * G];
__device__ __align__(256) float g_GF[G * 128];
__device__ float g_msg[G * 128];
__device__ float g_deg[G];
__device__ float g_norm[G];
__device__ float g_red[2 * 65];
__device__ float g_uvec[2 * 64];
__device__ float g_ccon[2];

// ---------------- PTX helpers (base compute_103 — no 'a'-features) ----------------
__device__ __forceinline__ uint32_t smem_u32(const void* p) {
    uint32_t a;
    asm("{ .reg .u64 t; cvta.to.shared.u64 t, %1; cvt.u32.u64 %0, t; }" : "=r"(a) : "l"(p));
    return a;
}
__device__ __forceinline__ void cpasync16(uint32_t dst, const void* src) {
    asm volatile("cp.async.cg.shared.global [%0], [%1], 16;" :: "r"(dst), "l"(src) : "memory");
}
#define CP_COMMIT() asm volatile("cp.async.commit_group;" ::: "memory")
#define CP_WAIT1()  asm volatile("cp.async.wait_group 1;" ::: "memory")

__device__ __forceinline__ void ldsm4(uint32_t& r0, uint32_t& r1, uint32_t& r2, uint32_t& r3,
                                      uint32_t addr) {
    asm volatile("ldmatrix.sync.aligned.m8n8.x4.shared.b16 {%0,%1,%2,%3}, [%4];"
                 : "=r"(r0), "=r"(r1), "=r"(r2), "=r"(r3) : "r"(addr));
}
__device__ __forceinline__ void mma16816(float* c, const uint32_t* a, const uint32_t* b) {
    asm volatile(
        "mma.sync.aligned.m16n8k16.row.col.f32.bf16.bf16.f32 "
        "{%0,%1,%2,%3}, {%4,%5,%6,%7}, {%8,%9}, {%0,%1,%2,%3};"
        : "+f"(c[0]), "+f"(c[1]), "+f"(c[2]), "+f"(c[3])
        : "r"(a[0]), "r"(a[1]), "r"(a[2]), "r"(a[3]), "r"(b[0]), "r"(b[1]));
}

// ---------------- k_zero ----------------
__global__ void k_zero() {
    int i = blockIdx.x * blockDim.x + threadIdx.x;
    if (i < 2 * 65) g_red[i] = 0.f;
    if (i < 2 * G) { g_Z[i] = 0.f; g_cnt[i] = 0; }
}

// ---------------- k_reduce: r = sum_m Ws[m] x[m,:], sw = sum Ws ----------------
__global__ void k_reduce(const float* __restrict__ x,
                         const float* __restrict__ uWs,
                         const float* __restrict__ iWs) {
    int half = blockIdx.y;
    int m0 = blockIdx.x * 500;
    int Nh = half ? NI : NU;
    if (m0 >= Nh) return;
    const float* Ws = half ? iWs : uWs;
    int off = half ? NU : 0;
    int md = threadIdx.x >> 6;
    int dd = threadIdx.x & 63;
    float acc = 0.f, sw = 0.f;
    int m1 = min(m0 + 500, Nh);
    for (int m = m0 + md; m < m1; m += 4) {
        float w = Ws[m];
        acc += w * x[(size_t)(off + m) * 64 + dd];
        if (dd == 0) sw += w;
    }
    __shared__ float sA[4][64];
    __shared__ float sW[4];
    sA[md][dd] = acc;
    if (dd == 0) sW[md] = sw;
    __syncthreads();
    if (md == 0) {
        float t = sA[0][dd] + sA[1][dd] + sA[2][dd] + sA[3][dd];
        atomicAdd(&g_red[half * 65 + dd], t);
        if (dd == 0) atomicAdd(&g_red[half * 65 + 64], sW[0] + sW[1] + sW[2] + sW[3]);
    }
}

// ---------------- k_prep ----------------
__global__ void k_prep(const float* __restrict__ uWk, const float* __restrict__ ubk,
                       const float* __restrict__ uWq, const float* __restrict__ ubq,
                       const float* __restrict__ ubs,
                       const float* __restrict__ iWk, const float* __restrict__ ibk,
                       const float* __restrict__ iWq, const float* __restrict__ ibq,
                       const float* __restrict__ ibs) {
    __shared__ float rS[64], tS[64];
    int t = threadIdx.x;
    for (int half = 0; half < 2; half++) {
        const float* Wk = half ? iWk : uWk; const float* bk = half ? ibk : ubk;
        const float* Wq = half ? iWq : uWq; const float* bq = half ? ibq : ubq;
        const float* bs = half ? ibs : ubs;
        rS[t] = g_red[half * 65 + t];
        __syncthreads();
        float sw = g_red[half * 65 + 64];
        float tv = 0.f;
        for (int d = 0; d < 64; d++) tv += Wk[t * 64 + d] * rS[d];
        tv += sw * bk[t];
        tS[t] = tv;
        __syncthreads();
        float u = 0.f;
        for (int hd = 0; hd < 64; hd++) u += Wq[hd * 64 + t] * tS[hd];
        g_uvec[half * 64 + t] = u;
        if (t == 0) {
            float c = bs[0];
            for (int hd = 0; hd < 64; hd++) c += bq[hd] * tS[hd];
            g_ccon[half] = c;
        }
        __syncthreads();
    }
}

// ---------------- k_ev: V rows + E=exp(s) (32 rows per block) ----------------
__global__ __launch_bounds__(256) void k_ev(const float* __restrict__ x,
                     const float* __restrict__ uWv, const float* __restrict__ ubv,
                     const float* __restrict__ iWv, const float* __restrict__ ibv) {
    int r0 = blockIdx.x * 32;
    int half = (r0 >= NU) ? 1 : 0;
    const float* Wv = half ? iWv : uWv;
    const float* bv = half ? ibv : ubv;
    __shared__ float wS[64][65];
    __shared__ float xS[32][65];
    __shared__ float bS[64], uS[64];
    int tid = threadIdx.x;
    for (int i = tid; i < 4096; i += 256) wS[i >> 6][i & 63] = Wv[i];
    if (tid < 64) { bS[tid] = bv[tid]; uS[tid] = g_uvec[half * 64 + tid]; }
    for (int i = tid; i < 2048; i += 256) {
        int rr = i >> 6;
        int gr = r0 + rr;
        xS[rr][i & 63] = (gr < NT) ? x[(size_t)gr * 64 + (i & 63)] : 0.f;
    }
    __syncthreads();
    int row = tid >> 3;
    int c0 = (tid & 7) * 8;
    float v[8];
    #pragma unroll
    for (int j = 0; j < 8; j++) v[j] = bS[c0 + j];
    #pragma unroll 8
    for (int d = 0; d < 64; d++) {
        float xv = xS[row][d];
        #pragma unroll
        for (int j = 0; j < 8; j++) v[j] += wS[c0 + j][d] * xv;
    }
    int gr = r0 + row;
    if (gr < NT) {
        #pragma unroll
        for (int j = 0; j < 8; j++) g_V[(size_t)gr * 64 + c0 + j] = v[j];
    }
    float p = 0.f;
    #pragma unroll
    for (int j = 0; j < 8; j++) p += xS[row][c0 + j] * uS[c0 + j];
    p += __shfl_xor_sync(0xffffffff, p, 1);
    p += __shfl_xor_sync(0xffffffff, p, 2);
    p += __shfl_xor_sync(0xffffffff, p, 4);
    if ((tid & 7) == 0 && gr < NT) g_E[gr] = expf(p + g_ccon[half]);
}

// ---------------- k_z: Z_g and counts per half ----------------
__global__ void k_z(const int* __restrict__ H) {
    int gcol = blockIdx.x * 256 + threadIdx.x;
    int n0 = blockIdx.y * 1000;
    int half = (n0 >= NU) ? 1 : 0;
    __shared__ float eS[1000];
    for (int i = threadIdx.x; i < 1000; i += 256) eS[i] = g_E[n0 + i];
    __syncthreads();
    float z = 0.f; int c = 0;
    const int* Hp = H + (size_t)n0 * G + gcol;
    for (int i = 0; i < 1000; i++) {
        if (Hp[(size_t)i * G] != 0) { z += eS[i]; c++; }
    }
    atomicAdd(&g_Z[half * G + gcol], z);
    atomicAdd(&g_cnt[half * G + gcol], c);
}

// ---------------- k_inv ----------------
__global__ void k_inv() {
    int i = blockIdx.x * 256 + threadIdx.x;
    if (i < 2 * G) {
        int c = g_cnt[i];
        g_iZ[i] = (c > 0) ? 1.f / g_Z[i] : 0.f;
        g_degf[i] = (c == 0) ? 1 : 0;
    }
}

// ---------------- k_pack: A = bf16(m*E^2), M = m (K-major panels) ----------------
__global__ __launch_bounds__(256) void k_pack(const int* __restrict__ H) {
    int g0 = blockIdx.x * 128;
    int n0 = blockIdx.y * 64;
    bool half_i = (n0 >= KPU);
    __shared__ float e2s[64];
    __shared__ int gns[64];
    int tid = threadIdx.x;
    if (tid < 64) {
        int n = n0 + tid;
        int gn;
        if (!half_i) gn = (n < NU) ? n : -1;
        else { int k = n - KPU; gn = (k < NI) ? (NU + k) : -1; }
        gns[tid] = gn;
        float e = (gn >= 0) ? g_E[gn] : 0.f;
        e2s[tid] = e * e;
    }
    __syncthreads();
    int gl = tid & 127;
    int g = g0 + gl;
    bool dead = (g_cnt[(half_i ? G : 0) + g] == 0);
    int cgrp = tid >> 7;
    union U8 { __nv_bfloat16 h[8]; uint4 v; };
    for (int q = 0; q < 4; q++) {
        int ck = cgrp * 4 + q;
        U8 ua, um;
        #pragma unroll
        for (int j = 0; j < 8; j++) {
            int nl = ck * 8 + j;
            int gn = gns[nl];
            float a = 0.f;
            float mv = 0.f;
            if (gn >= 0 && !dead) {
                int h = H[(size_t)gn * G + g];
                if (h != 0) { a = e2s[nl]; mv = 1.f; }
            }
            ua.h[j] = __float2bfloat16(a);
            um.h[j] = __float2bfloat16(mv);
        }
        size_t off = (size_t)g * KP + n0 + ck * 8;
        *(uint4*)&g_A[off] = ua.v;
        *(uint4*)&g_M[off] = um.v;
    }
}

// ---------------- k_w: W[c][n] = bf16(E[n]*R2[n][c]) ----------------
__global__ __launch_bounds__(256) void k_w() {
    int n0 = blockIdx.x * 64;
    bool half_i = (n0 >= KPU);
    __shared__ float es[64];
    __shared__ int gns[64];
    int tid = threadIdx.x;
    if (tid < 64) {
        int n = n0 + tid;
        int gn;
        if (!half_i) gn = (n < NU) ? n : -1;
        else { int k = n - KPU; gn = (k < NI) ? (NU + k) : -1; }
        gns[tid] = gn;
        es[tid] = (gn >= 0) ? g_E[gn] : 0.f;
    }
    __syncthreads();
    int c = tid & 127;
    int cgrp = tid >> 7;
    bool active = half_i ? (c >= 64) : (c < 64);
    int vc = half_i ? (c - 64) : c;
    union U8 { __nv_bfloat16 h[8]; uint4 v; };
    for (int q = 0; q < 4; q++) {
        int ck = cgrp * 4 + q;
        U8 uh;
        #pragma unroll
        for (int j = 0; j < 8; j++) {
            int nl = ck * 8 + j;
            int gn = gns[nl];
            float w = 0.f;
            if (active && gn >= 0) w = es[nl] * g_V[(size_t)gn * 64 + vc];
            uh.h[j] = __float2bfloat16(w);
        }
        size_t off = (size_t)c * KP + n0 + ck * 8;
        *(uint4*)&g_W[off] = uh.v;
    }
}

// ---------------- k_csv: column sums of V per half ----------------
__global__ void k_csv() {
    int half = blockIdx.x;
    int c = threadIdx.x & 63;
    int seg = threadIdx.x >> 6;
    int lo = half ? NU : 0, hi = half ? NT : NU;
    float s = 0.f;
    for (int r = lo + seg; r < hi; r += 4) s += g_V[(size_t)r * 64 + c];
    __shared__ float red[4][64];
    red[seg][c] = s;
    __syncthreads();
    if (seg == 0) g_csV[half * 64 + c] = red[0][c] + red[1][c] + red[2][c] + red[3][c];
}

// ---------------- k_mma: single-GEMM HMMA SYRK + GF panels, 2 CTA/SM ----------------
// SYRK tile (bi,bj): A(gi) x M(gj)^T; u-phase flushed scaled mid-loop, i-phase in epilogue.
// GF block: M(gi) x W^T.
__global__ __launch_bounds__(256, 2) void k_mma() {
    extern __shared__ char smem[];
    uint32_t sb = smem_u32(smem);
    int tid = threadIdx.x;
    int wid = tid >> 5;
    int lane = tid & 31;

    int blk = blockIdx.x;
    int bi, bj;
    bool gfm;
    if (blk < 528) {
        int l = blk; bi = 0;
        while (l > bi) { l -= (bi + 1); bi++; }
        bj = l; gfm = false;
    } else {
        bi = blk - 528; bj = 0; gfm = true;
    }
    int gi0 = bi * 128, gj0 = bj * 128;

    // ---- loader setup: 4 x 16B per thread per stage ----
    uint32_t dstoff[4];
    const char* srcp[4];
    #pragma unroll
    for (int i = 0; i < 4; i++) {
        int flat = tid + i * 256;
        int mat = flat >> 9;            // 0..1
        int row = (flat >> 2) & 127;
        int ch  = flat & 3;
        const __nv_bfloat16* bas;
        if (!gfm) {
            bas = (mat == 0) ? g_A + (size_t)(gi0 + row) * KP
                             : g_M + (size_t)(gj0 + row) * KP;
        } else {
            bas = (mat == 0) ? g_M + (size_t)(gi0 + row) * KP
                             : g_W + (size_t)row * KP;
        }
        srcp[i] = (const char*)(bas + ch * 8);
        dstoff[i] = (uint32_t)(mat * MAT_SZ + row * 64 + ((ch ^ ((row >> 1) & 3)) << 4));
    }

    // ---- single accumulator set ----
    float acc[2][8][4];
    #pragma unroll
    for (int a = 0; a < 2; a++)
        #pragma unroll
        for (int b = 0; b < 8; b++)
            #pragma unroll
            for (int c = 0; c < 4; c++) acc[a][b][c] = 0.f;

    int wm = wid & 3, wn = wid >> 2;
    int mr0 = wm * 32, nr0 = wn * 64;
    int gid = lane >> 2, qc = (lane & 3) * 2;

    // prologue: stages 0,1
    #pragma unroll
    for (int i = 0; i < 4; i++) cpasync16(sb + dstoff[i], srcp[i]);
    CP_COMMIT();
    #pragma unroll
    for (int i = 0; i < 4; i++) cpasync16(sb + STG + dstoff[i], srcp[i] + KC * 2);
    CP_COMMIT();

    for (int step = 0; step < NSTEP; step++) {
        CP_WAIT1();
        __syncthreads();
        if (step + 2 < NSTEP) {
            uint32_t dstage = sb + (uint32_t)((step + 2) % 3) * STG;
            size_t soff = (size_t)(step + 2) * (KC * 2);
            #pragma unroll
            for (int i = 0; i < 4; i++) cpasync16(dstage + dstoff[i], srcp[i] + soff);
        }
        CP_COMMIT();

        uint32_t mb = sb + (uint32_t)(step % 3) * STG;
        uint32_t m0b = mb, m1b = mb + MAT_SZ;

        #define LDA(FR, MB, MR, KI) { \
            int _r = (MR) + (lane & 15); \
            int _c = 2 * (KI) + (lane >> 4); \
            ldsm4(FR[0], FR[1], FR[2], FR[3], (MB) + _r * 64 + (((_c) ^ ((_r >> 1) & 3)) << 4)); }
        #define LDB(FR, MB, NR, KI) { \
            int _r = (NR) + (lane & 7) + ((lane >> 4) & 1) * 8; \
            int _c = 2 * (KI) + ((lane >> 3) & 1); \
            ldsm4(FR[0], FR[1], FR[2], FR[3], (MB) + _r * 64 + (((_c) ^ ((_r >> 1) & 3)) << 4)); }

        #define MMA_K16(ACC, KI) { \
            uint32_t aa[2][4], bb[4][4]; \
            LDA(aa[0], m0b, mr0, KI); LDA(aa[1], m0b, mr0 + 16, KI); \
            LDB(bb[0], m1b, nr0, KI); LDB(bb[1], m1b, nr0 + 16, KI); \
            LDB(bb[2], m1b, nr0 + 32, KI); LDB(bb[3], m1b, nr0 + 48, KI); \
            _Pragma("unroll") \
            for (int mi = 0; mi < 2; mi++) \
                _Pragma("unroll") \
                for (int t = 0; t < 4; t++) \
                    _Pragma("unroll") \
                    for (int s2 = 0; s2 < 2; s2++) \
                        mma16816(ACC[mi][t * 2 + s2], aa[mi], &bb[t][2 * s2]); }

        MMA_K16(acc, 0); MMA_K16(acc, 1);

        if (!gfm && step == STEP_U - 1) {
            // ---- mid-loop flush of scaled u-partial (regs + gmem only) ----
            #pragma unroll
            for (int mi = 0; mi < 2; mi++) {
                #pragma unroll
                for (int rh = 0; rh < 2; rh++) {
                    int r = gi0 + mr0 + mi * 16 + gid + rh * 8;
                    float gzu = g_iZ[r];
                    int gfu = g_degf[r];
                    #pragma unroll
                    for (int nj = 0; nj < 8; nj++) {
                        #pragma unroll
                        for (int e = 0; e < 2; e++) {
                            int h = gj0 + nr0 + nj * 8 + qc + e;
                            float su = acc[mi][nj][rh * 2 + e];
                            float tu = (gfu | g_degf[h]) ? INV_NU : su * gzu * g_iZ[h];
                            g_wp[(size_t)r * G + h] = tu;
                            acc[mi][nj][rh * 2 + e] = 0.f;
                        }
                    }
                }
            }
        }
    }
    __syncthreads();

    // ---- epilogue ----
    float* szi  = (float*)(smem + 0);
    int*   sfl  = (int*)  (smem + 512);
    float* scsv = (float*)(smem + 1024);
    if (tid < 128) {
        if (!gfm) {
            int h = gj0 + tid;
            szi[tid] = g_iZ[G + h];
            sfl[tid] = g_degf[G + h] ? 1 : 0;
        } else {
            scsv[tid] = g_csV[tid];
        }
    }
    __syncthreads();

    if (!gfm) {
        #pragma unroll
        for (int mi = 0; mi < 2; mi++) {
            #pragma unroll
            for (int rh = 0; rh < 2; rh++) {
                int r = gi0 + mr0 + mi * 16 + gid + rh * 8;
                float gzi = g_iZ[G + r];
                int gfi = g_degf[G + r];
                #pragma unroll
                for (int nj = 0; nj < 8; nj++) {
                    #pragma unroll
                    for (int e = 0; e < 2; e++) {
                        int cl = nr0 + nj * 8 + qc + e;
                        float si = acc[mi][nj][rh * 2 + e];
                        float ti = (gfi | sfl[cl]) ? INV_NI : si * gzi * szi[cl];
                        float v = g_wp[(size_t)r * G + gj0 + cl] + ti;
                        g_wp[(size_t)r * G + gj0 + cl] = v;
                        if (bi != bj) g_wp[(size_t)(gj0 + cl) * G + r] = v;
                    }
                }
            }
        }
    } else {
        #pragma unroll
        for (int mi = 0; mi < 2; mi++) {
            #pragma unroll
            for (int rh = 0; rh < 2; rh++) {
                int r = gi0 + mr0 + mi * 16 + gid + rh * 8;
                float gzu = g_iZ[r], gzi = g_iZ[G + r];
                int gfl = (g_degf[r] ? 1 : 0) | (g_degf[G + r] ? 2 : 0);
                #pragma unroll
                for (int nj = 0; nj < 8; nj++) {
                    #pragma unroll
                    for (int e = 0; e < 2; e++) {
                        int cl = nr0 + nj * 8 + qc + e;
                        float a = acc[mi][nj][rh * 2 + e];
                        float v = (cl < 64)
                            ? ((gfl & 1) ? INV_NU * scsv[cl] : a * gzu)
                            : ((gfl & 2) ? INV_NI * scsv[cl] : a * gzi);
                        g_GF[(size_t)r * 128 + cl] = v;
                    }
                }
            }
        }
    }
}

// ---------------- k_norm ----------------
__global__ void k_norm() {
    int g = blockIdx.x * 256 + threadIdx.x;
    if (g < G) g_norm[g] = sqrtf(g_wp[(size_t)g * G + g]);
}

// ---------------- k_msg ----------------
__global__ void k_msg() {
    int h0 = blockIdx.x * 32;
    int tx = threadIdx.x & 15, ty = threadIdx.x >> 4;
    __shared__ float wpS[32][17];
    __shared__ float gfS[16][128];
    __shared__ float nS[16];
    float nh0 = g_norm[h0 + ty * 2];
    float nh1 = g_norm[h0 + ty * 2 + 1];
    float macc[2][8];
    #pragma unroll
    for (int i = 0; i < 2; i++)
        #pragma unroll
        for (int j = 0; j < 8; j++) macc[i][j] = 0.f;
    float dacc[2] = {0.f, 0.f};
    int lrow = threadIdx.x >> 5, lc4 = (threadIdx.x & 31) * 4;
    int wrow = threadIdx.x >> 3, wcol = (threadIdx.x & 7) * 2;

    for (int k0 = 0; k0 < G; k0 += 16) {
        float2 wv = *(const float2*)&g_wp[(size_t)(h0 + wrow) * G + k0 + wcol];
        wpS[wrow][wcol] = wv.x;
        wpS[wrow][wcol + 1] = wv.y;
        *(float4*)&gfS[lrow][lc4]     = *(const float4*)&g_GF[(size_t)(k0 + lrow) * 128 + lc4];
        *(float4*)&gfS[lrow + 8][lc4] = *(const float4*)&g_GF[(size_t)(k0 + lrow + 8) * 128 + lc4];
        if (threadIdx.x < 16) nS[threadIdx.x] = g_norm[k0 + threadIdx.x];
        __syncthreads();
        #pragma unroll
        for (int kk = 0; kk < 16; kk++) {
            float ng = nS[kk];
            float a0 = __fdividef(wpS[ty * 2][kk],     nh0 * ng + EPSL);
            float a1 = __fdividef(wpS[ty * 2 + 1][kk], nh1 * ng + EPSL);
            dacc[0] += a0; dacc[1] += a1;
            #pragma unroll
            for (int j = 0; j < 8; j++) {
                float b = gfS[kk][tx * 8 + j];
                macc[0][j] += a0 * b;
                macc[1][j] += a1 * b;
            }
        }
        __syncthreads();
    }
    #pragma unroll
    for (int ii = 0; ii < 2; ii++) {
        int h = h0 + ty * 2 + ii;
        #pragma unroll
        for (int j = 0; j < 8; j++) g_msg[h * 128 + tx * 8 + j] = macc[ii][j];
        if (tx == 0) g_deg[h] = dacc[ii];
    }
}

// ---------------- k_out ----------------
__global__ void k_out(const float* __restrict__ gW, const float* __restrict__ gb,
                      float* __restrict__ out) {
    int g = blockIdx.x;
    int t = threadIdx.x;
    __shared__ float aggS[128];
    float dg = g_deg[g];
    float invd = (dg > 0.f) ? 1.f / dg : 0.f;
    for (int c = t; c < 128; c += 64) {
        float hn = g_msg[g * 128 + c] * invd;
        aggS[c] = ALPHA * g_GF[g * 128 + c] + (1.f - ALPHA) * hn;
    }
    __syncthreads();
    float acc = gb[t];
    #pragma unroll
    for (int c = 0; c < 128; c++) acc += aggS[c] * gW[t * 128 + c];
    out[g * 64 + t] = 1.f / (1.f + expf(-acc));
}

// ---------------- launch ----------------
extern "C" void kernel_launch(void* const* d_in, const int* in_sizes, int n_in,
                              void* d_out, int out_size) {
    int base = (in_sizes[2] == 1) ? 3 : 2;
    const int*   H   = (const int*)d_in[0];
    const float* X   = (const float*)d_in[1];
    const float* uWq = (const float*)d_in[base + 0];
    const float* ubq = (const float*)d_in[base + 1];
    const float* uWk = (const float*)d_in[base + 2];
    const float* ubk = (const float*)d_in[base + 3];
    const float* uWv = (const float*)d_in[base + 4];
    const float* ubv = (const float*)d_in[base + 5];
    const float* uWs = (const float*)d_in[base + 6];
    const float* ubs = (const float*)d_in[base + 7];
    const float* iWq = (const float*)d_in[base + 8];
    const float* ibq = (const float*)d_in[base + 9];
    const float* iWk = (const float*)d_in[base + 10];
    const float* ibk = (const float*)d_in[base + 11];
    const float* iWv = (const float*)d_in[base + 12];
    const float* ibv = (const float*)d_in[base + 13];
    const float* iWs = (const float*)d_in[base + 14];
    const float* ibs = (const float*)d_in[base + 15];
    const float* gW  = (const float*)d_in[base + 16];
    const float* gb  = (const float*)d_in[base + 17];
    float* out = (float*)d_out;

    static int smem_set = 0;
    if (!smem_set) {
        cudaFuncSetAttribute(k_mma, cudaFuncAttributeMaxDynamicSharedMemorySize, SMEM_MMA);
        smem_set = 1;
    }

    k_zero<<<32, 256>>>();
    k_reduce<<<dim3(20, 2), 256>>>(X, uWs, iWs);
    k_prep<<<1, 64>>>(uWk, ubk, uWq, ubq, ubs, iWk, ibk, iWq, ibq, ibs);
    k_ev<<<563, 256>>>(X, uWv, ubv, iWv, ibv);
    k_z<<<dim3(16, 18), 256>>>(H);
    k_inv<<<32, 256>>>();
    k_pack<<<dim3(32, 283), 256>>>(H);
    k_w<<<283, 256>>>();
    k_csv<<<2, 256>>>();
    k_mma<<<560, 256, SMEM_MMA>>>();
    k_norm<<<16, 256>>>();
    k_msg<<<128, 256>>>();
    k_out<<<G, 64>>>(gW, gb, out);
}